// round 10
// baseline (speedup 1.0000x reference)
#include <cuda_runtime.h>
#include <cstdint>

#define BSZ  256
#define TSEQ 512
#define HIDN 256

typedef unsigned long long ull;

// ---- static scratch ----
// xg layout: [t][b][n][4] (gate quads)
__device__ float g_xg[(size_t)TSEQ * BSZ * 1024];
__device__ float g_hist0[(size_t)TSEQ * BSZ * HIDN];
__device__ float g_hist1[(size_t)TSEQ * BSZ * HIDN];
__device__ unsigned g_bar[256];   // [bi][ga][ni]

__global__ void reset_bar() { if (threadIdx.x < 256) g_bar[threadIdx.x] = 0u; }

__device__ __forceinline__ float sigm(float x) { return 1.f / (1.f + __expf(-x)); }
__device__ __forceinline__ float ftanh(float x) {
    float e = __expf(-2.f * fabsf(x));
    return copysignf((1.f - e) / (1.f + e), x);
}

// ---- packed fp32x2 (Blackwell) ----
__device__ __forceinline__ ull ffma2(ull a, ull b, ull c) {
    ull d; asm("fma.rn.f32x2 %0, %1, %2, %3;" : "=l"(d) : "l"(a), "l"(b), "l"(c)); return d;
}
__device__ __forceinline__ ull add2(ull a, ull b) {
    ull d; asm("add.rn.f32x2 %0, %1, %2;" : "=l"(d) : "l"(a), "l"(b)); return d;
}
__device__ __forceinline__ ull dup2(float x) {
    ull r; asm("mov.b64 %0, {%1, %1};" : "=l"(r) : "f"(x)); return r;
}
__device__ __forceinline__ float2 unpk(ull v) {
    float2 f; asm("mov.b64 {%0, %1}, %2;" : "=f"(f.x), "=f"(f.y) : "l"(v)); return f;
}

// ---- scoped sync ----
__device__ __forceinline__ unsigned ld_acq(const unsigned* p) {
    unsigned v; asm volatile("ld.acquire.gpu.global.b32 %0, [%1];" : "=r"(v) : "l"(p)); return v;
}
__device__ __forceinline__ void red_rel_add(unsigned* p, unsigned v) {
    asm volatile("red.release.gpu.global.add.u32 [%0], %1;" :: "l"(p), "r"(v) : "memory");
}

// ---- GEMM: xg[m*256 + n] (float4 gate quad) = A_row(m).W[g*256+n] + biases ----
template<int K, bool XMODE>
__global__ void __launch_bounds__(256, 2) gemm_xg(
    const float* __restrict__ A, const float* __restrict__ W,
    const float* __restrict__ b1, const float* __restrict__ b2,
    float* __restrict__ out)
{
    __shared__ float As[16][132];
    __shared__ float Ws[16][132];   // c = g*32 + (n-n0)
    const int m0 = blockIdx.x * 128, n0 = blockIdx.y * 32;
    const int tid = threadIdx.x;
    const int tm = tid >> 4, tn = tid & 15;

    int rrv[2], kqv[2];
#pragma unroll
    for (int i = 0; i < 2; i++) { int idx = tid + (i << 8); rrv[i] = idx >> 2; kqv[i] = (idx & 3) << 2; }
    size_t aoffv[2], woffv[2];
#pragma unroll
    for (int i = 0; i < 2; i++) {
        int row = m0 + rrv[i];
        if (XMODE) aoffv[i] = ((size_t)(row & 255) * TSEQ + (row >> 8)) * K;
        else       aoffv[i] = (size_t)row * K;
        int wrow = ((rrv[i] >> 5) << 8) + n0 + (rrv[i] & 31);
        woffv[i] = (size_t)wrow * K;
    }

    ull acc[8][4];
#pragma unroll
    for (int i = 0; i < 8; i++)
#pragma unroll
        for (int j = 0; j < 4; j++) acc[i][j] = 0ull;

    float4 pa[2], pw[2];
#pragma unroll
    for (int i = 0; i < 2; i++) {
        pa[i] = *reinterpret_cast<const float4*>(A + aoffv[i] + kqv[i]);
        pw[i] = *reinterpret_cast<const float4*>(W + woffv[i] + kqv[i]);
    }

    for (int kt = 0; kt < K; kt += 16) {
#pragma unroll
        for (int i = 0; i < 2; i++) {
            int k = kqv[i], rr = rrv[i];
            As[k+0][rr]=pa[i].x; As[k+1][rr]=pa[i].y; As[k+2][rr]=pa[i].z; As[k+3][rr]=pa[i].w;
            Ws[k+0][rr]=pw[i].x; Ws[k+1][rr]=pw[i].y; Ws[k+2][rr]=pw[i].z; Ws[k+3][rr]=pw[i].w;
        }
        __syncthreads();
        if (kt + 16 < K) {
#pragma unroll
            for (int i = 0; i < 2; i++) {
                pa[i] = *reinterpret_cast<const float4*>(A + aoffv[i] + kt + 16 + kqv[i]);
                pw[i] = *reinterpret_cast<const float4*>(W + woffv[i] + kt + 16 + kqv[i]);
            }
        }
#pragma unroll
        for (int k = 0; k < 16; k++) {
            float a[8];
            *reinterpret_cast<float4*>(&a[0]) = *reinterpret_cast<const float4*>(&As[k][tm << 3]);
            *reinterpret_cast<float4*>(&a[4]) = *reinterpret_cast<const float4*>(&As[k][(tm << 3) + 4]);
            ull w2[4];
#pragma unroll
            for (int g = 0; g < 4; g++)
                w2[g] = *reinterpret_cast<const ull*>(&Ws[k][(g << 5) + (tn << 1)]);
#pragma unroll
            for (int i = 0; i < 8; i++) {
                ull ad = dup2(a[i]);
#pragma unroll
                for (int g = 0; g < 4; g++) acc[i][g] = ffma2(ad, w2[g], acc[i][g]);
            }
        }
        __syncthreads();
    }

    const int n = n0 + (tn << 1);
    float bv0[4], bv1[4];
#pragma unroll
    for (int g = 0; g < 4; g++) {
        bv0[g] = b1[(g << 8) + n]     + b2[(g << 8) + n];
        bv1[g] = b1[(g << 8) + n + 1] + b2[(g << 8) + n + 1];
    }
    float4* out4 = reinterpret_cast<float4*>(out);
#pragma unroll
    for (int i = 0; i < 8; i++) {
        int m = m0 + (tm << 3) + i;
        float2 q0 = unpk(acc[i][0]), q1 = unpk(acc[i][1]);
        float2 q2 = unpk(acc[i][2]), q3 = unpk(acc[i][3]);
        out4[(size_t)m * 256 + n]     = make_float4(q0.x+bv0[0], q1.x+bv0[1], q2.x+bv0[2], q3.x+bv0[3]);
        out4[(size_t)m * 256 + n + 1] = make_float4(q0.y+bv1[0], q1.y+bv1[1], q2.y+bv1[2], q3.y+bv1[3]);
    }
}

// ---- persistent LSTM recurrence, dual-ring interleaved ----
// 128 CTAs = 16 bi x 8 ni. CTA handles TWO 8-batch groups (ga=0: 16bi..+8, ga=1: +8..+16)
// over the SAME W slice. Per iteration: step t of A then step t of B; each group's
// handoff latency hides under the other group's compute.
__global__ void __launch_bounds__(256, 1) rec_kernel(
    const float* __restrict__ xg, const float* __restrict__ Whh,
    float* __restrict__ hist)
{
    extern __shared__ float sm[];
    float* Wsh = sm;            // [k][nn*4+g]  32768 floats
    float* hsh = Wsh + 32768;   // 8 warps x [8][36] = 2304
    float* red = hsh + 2304;    // [kg][cell][4], 256 cells = 8192

    const int bi = blockIdx.x >> 3, ni = blockIdx.x & 7;
    const int n0 = ni << 5;
    const int tid = threadIdx.x;
    const int kg  = tid >> 5;
    const int cid = tid & 31;
    const int bb  = (cid >> 4) << 2;     // 0 or 4 (4 batches per lane-half)
    const int pn  = cid & 15;

    // Wsh[k][nn*4+g] = Whh[g*256 + n0 + nn][k]
    for (int idx = tid; idx < 8192; idx += 256) {
        int kq = idx & 63, c = idx >> 6;
        int nn = c >> 2, g = c & 3;
        float4 v = *reinterpret_cast<const float4*>(
            Whh + (size_t)((g << 8) + n0 + nn) * HIDN + (kq << 2));
        int k = kq << 2;
        Wsh[(k+0)*128+c]=v.x; Wsh[(k+1)*128+c]=v.y; Wsh[(k+2)*128+c]=v.z; Wsh[(k+3)*128+c]=v.w;
    }
    __syncthreads();

    // epilogue cell: 1 per thread. cell = b*32 + nn
    const int eb  = tid >> 5;            // 0..7
    const int enn = tid & 31;

    float* hshW = hsh + kg * 288;        // private [8][36]
    const float4* xg4 = reinterpret_cast<const float4*>(xg);
    float creg[2] = {0.f, 0.f};          // c for group A, B

    // counters: index ((bi*2+ga)*8 + ni)
    const unsigned* prodA = g_bar + ((bi << 4) | kg);        // ga=0, producer ni==kg
    const unsigned* prodB = g_bar + ((bi << 4) | 8 | kg);    // ga=1
    unsigned* mineA = g_bar + ((bi << 4) | ni);
    unsigned* mineB = g_bar + ((bi << 4) | 8 | ni);

    for (int t = 0; t < TSEQ; t++) {
        const unsigned tgt = (unsigned)t;

#pragma unroll
        for (int ga = 0; ga < 2; ga++) {
            const int b0g = (bi << 4) + (ga << 3);

            // prefetch this group's gate quad (independent of h)
            float4 xv = __ldg(&xg4[((size_t)t * BSZ + b0g + eb) * 256 + n0 + enn]);

            ull acc2[4][4];
#pragma unroll
            for (int i = 0; i < 4; i++)
#pragma unroll
                for (int j = 0; j < 4; j++) acc2[i][j] = 0ull;

            if (t > 0) {
                // warp waits only on its own producer for this ring
                const unsigned* pc = ga ? prodB : prodA;
                while (ld_acq(pc) < tgt) {}

                // stage own k-slice: 8 batches x 32 k (warp-private, 2 float4/lane)
                const float* hp = hist + ((size_t)(t - 1) * BSZ + b0g) * HIDN + (kg << 5);
#pragma unroll
                for (int i = 0; i < 2; i++) {
                    int f  = cid + (i << 5);        // 0..63
                    int b  = f >> 3, c4 = (f & 7) << 2;
                    *reinterpret_cast<float4*>(hshW + b * 36 + c4) =
                        *reinterpret_cast<const float4*>(hp + (b << 8) + c4);
                }
                __syncwarp();

                const float* hpL = hshW + bb * 36;
                const float* wp  = Wsh + ((kg << 5) * 128) + (pn << 3);
#pragma unroll 8
                for (int k = 0; k < 32; k++) {
                    ulonglong2 wa = *reinterpret_cast<const ulonglong2*>(wp);
                    ulonglong2 wb = *reinterpret_cast<const ulonglong2*>(wp + 4);
                    wp += 128;
#pragma unroll
                    for (int i = 0; i < 4; i++) {
                        ull hd = dup2(hpL[i * 36 + k]);
                        acc2[i][0] = ffma2(hd, wa.x, acc2[i][0]);
                        acc2[i][1] = ffma2(hd, wa.y, acc2[i][1]);
                        acc2[i][2] = ffma2(hd, wb.x, acc2[i][2]);
                        acc2[i][3] = ffma2(hd, wb.y, acc2[i][3]);
                    }
                }
            }

            // gate-quad partials: red[kg][cell][4], cell = b*32+nn
#pragma unroll
            for (int i = 0; i < 4; i++) {
                int cell = ((bb + i) << 5) | (pn << 1);
                float* rp = red + (kg << 10) + (cell << 2);
                *reinterpret_cast<ulonglong2*>(rp)     = make_ulonglong2(acc2[i][0], acc2[i][1]);
                *reinterpret_cast<ulonglong2*>(rp + 4) = make_ulonglong2(acc2[i][2], acc2[i][3]);
            }
            __syncthreads();

            // epilogue: 1 cell/thread, c in registers
            {
                ull s01 = dup2(0.f), s23 = s01;
                {   // xq as two packed pairs
                    s01 = *reinterpret_cast<const ull*>(&xv.x);
                    s23 = *reinterpret_cast<const ull*>(&xv.z);
                }
                const float* rb = red + (tid << 2);
#pragma unroll
                for (int s = 0; s < 8; s++) {
                    ulonglong2 r = *reinterpret_cast<const ulonglong2*>(rb + (s << 10));
                    s01 = add2(s01, r.x);
                    s23 = add2(s23, r.y);
                }
                float2 g01 = unpk(s01), g23 = unpk(s23);
                float cn = sigm(g01.y) * creg[ga] + sigm(g01.x) * ftanh(g23.x);
                creg[ga] = cn;
                hist[((size_t)t * BSZ + b0g + eb) * HIDN + n0 + enn] = sigm(g23.y) * ftanh(cn);
            }
            __syncthreads();                            // h stores + red reads complete
            if (tid == 0) red_rel_add(ga ? mineB : mineA, 1u);
        }
    }
}

// ---- head ----
__global__ void head_kernel(const float* __restrict__ Wh, const float* __restrict__ bh,
                            float* __restrict__ out)
{
    __shared__ float rs[8];
    int b = blockIdx.x, tid = threadIdx.x;
    float v = g_hist1[((size_t)(TSEQ - 1) * BSZ + b) * HIDN + tid] * Wh[tid];
#pragma unroll
    for (int o = 16; o > 0; o >>= 1) v += __shfl_down_sync(0xffffffffu, v, o);
    if ((tid & 31) == 0) rs[tid >> 5] = v;
    __syncthreads();
    if (tid < 8) {
        float s = rs[tid];
#pragma unroll
        for (int o = 4; o > 0; o >>= 1) s += __shfl_down_sync(0xffu, s, o);
        if (tid == 0) out[b] = s + bh[0];
    }
}

extern "C" void kernel_launch(void* const* d_in, const int* in_sizes, int n_in,
                              void* d_out, int out_size)
{
    const float* x      = (const float*)d_in[0];
    const float* W_ih0  = (const float*)d_in[1];
    const float* W_hh0  = (const float*)d_in[2];
    const float* b_ih0  = (const float*)d_in[3];
    const float* b_hh0  = (const float*)d_in[4];
    const float* W_ih1  = (const float*)d_in[5];
    const float* W_hh1  = (const float*)d_in[6];
    const float* b_ih1  = (const float*)d_in[7];
    const float* b_hh1  = (const float*)d_in[8];
    const float* W_head = (const float*)d_in[9];
    const float* b_head = (const float*)d_in[10];
    float* out = (float*)d_out;

    void *pxg, *ph0, *ph1;
    cudaGetSymbolAddress(&pxg, g_xg);
    cudaGetSymbolAddress(&ph0, g_hist0);
    cudaGetSymbolAddress(&ph1, g_hist1);
    float* xg = (float*)pxg; float* h0 = (float*)ph0; float* h1 = (float*)ph1;

    const int SMEM = 43264 * 4;   // 173056 B
    cudaFuncSetAttribute(rec_kernel, cudaFuncAttributeMaxDynamicSharedMemorySize, SMEM);

    dim3 gg(1024, 8);
    gemm_xg<64,  true ><<<gg, 256>>>(x,  W_ih0, b_ih0, b_hh0, xg);
    reset_bar<<<1, 256>>>();
    rec_kernel<<<128, 256, SMEM>>>(xg, W_hh0, h0);
    gemm_xg<256, false><<<gg, 256>>>(h0, W_ih1, b_ih1, b_hh1, xg);
    reset_bar<<<1, 256>>>();
    rec_kernel<<<128, 256, SMEM>>>(xg, W_hh1, h1);
    head_kernel<<<256, 256>>>(W_head, b_head, out);
}

// round 11
// speedup vs baseline: 1.2938x; 1.2938x over previous
#include <cuda_runtime.h>
#include <cstdint>

#define BSZ  256
#define TSEQ 512
#define HIDN 256

typedef unsigned long long ull;

// ---- static scratch ----
// xg layout: [t][b][n][4] (gate quads)
__device__ float g_xg[(size_t)TSEQ * BSZ * 1024];
__device__ float g_hist0[(size_t)TSEQ * BSZ * HIDN];
__device__ float g_hist1[(size_t)TSEQ * BSZ * HIDN];
__device__ unsigned g_bar[128];   // [batch-group][producer ni]

__global__ void reset_bar() { if (threadIdx.x < 128) g_bar[threadIdx.x] = 0u; }

__device__ __forceinline__ float sigm(float x) { return 1.f / (1.f + __expf(-x)); }
__device__ __forceinline__ float ftanh(float x) {
    float e = __expf(-2.f * fabsf(x));
    return copysignf((1.f - e) / (1.f + e), x);
}

// ---- packed fp32x2 (Blackwell) ----
__device__ __forceinline__ ull ffma2(ull a, ull b, ull c) {
    ull d; asm("fma.rn.f32x2 %0, %1, %2, %3;" : "=l"(d) : "l"(a), "l"(b), "l"(c)); return d;
}
__device__ __forceinline__ ull add2(ull a, ull b) {
    ull d; asm("add.rn.f32x2 %0, %1, %2;" : "=l"(d) : "l"(a), "l"(b)); return d;
}
__device__ __forceinline__ ull dup2(float x) {
    ull r; asm("mov.b64 %0, {%1, %1};" : "=l"(r) : "f"(x)); return r;
}
__device__ __forceinline__ float2 unpk(ull v) {
    float2 f; asm("mov.b64 {%0, %1}, %2;" : "=f"(f.x), "=f"(f.y) : "l"(v)); return f;
}

// ---- scoped sync ----
__device__ __forceinline__ unsigned ld_acq(const unsigned* p) {
    unsigned v; asm volatile("ld.acquire.gpu.global.b32 %0, [%1];" : "=r"(v) : "l"(p)); return v;
}
__device__ __forceinline__ void red_rel_add(unsigned* p, unsigned v) {
    asm volatile("red.release.gpu.global.add.u32 [%0], %1;" :: "l"(p), "r"(v) : "memory");
}

// ---- cp.async staging ----
__device__ __forceinline__ uint32_t smem_u32(const void* p) {
    uint32_t a;
    asm("{ .reg .u64 t; cvta.to.shared.u64 t, %1; cvt.u32.u64 %0, t; }" : "=r"(a) : "l"(p));
    return a;
}
__device__ __forceinline__ void cp_async16(uint32_t dst, const void* src) {
    asm volatile("cp.async.ca.shared.global [%0], [%1], 16;" :: "r"(dst), "l"(src) : "memory");
}
__device__ __forceinline__ void cp_async_wait_all() {
    asm volatile("cp.async.wait_all;" ::: "memory");
}

// ---- GEMM: xg[m*256 + n] (float4 gate quad) = A_row(m).W[g*256+n] + biases ----
template<int K, bool XMODE>
__global__ void __launch_bounds__(256, 2) gemm_xg(
    const float* __restrict__ A, const float* __restrict__ W,
    const float* __restrict__ b1, const float* __restrict__ b2,
    float* __restrict__ out)
{
    __shared__ float As[16][132];
    __shared__ float Ws[16][132];   // c = g*32 + (n-n0)
    const int m0 = blockIdx.x * 128, n0 = blockIdx.y * 32;
    const int tid = threadIdx.x;
    const int tm = tid >> 4, tn = tid & 15;

    int rrv[2], kqv[2];
#pragma unroll
    for (int i = 0; i < 2; i++) { int idx = tid + (i << 8); rrv[i] = idx >> 2; kqv[i] = (idx & 3) << 2; }
    size_t aoffv[2], woffv[2];
#pragma unroll
    for (int i = 0; i < 2; i++) {
        int row = m0 + rrv[i];
        if (XMODE) aoffv[i] = ((size_t)(row & 255) * TSEQ + (row >> 8)) * K;
        else       aoffv[i] = (size_t)row * K;
        int wrow = ((rrv[i] >> 5) << 8) + n0 + (rrv[i] & 31);
        woffv[i] = (size_t)wrow * K;
    }

    ull acc[8][4];
#pragma unroll
    for (int i = 0; i < 8; i++)
#pragma unroll
        for (int j = 0; j < 4; j++) acc[i][j] = 0ull;

    float4 pa[2], pw[2];
#pragma unroll
    for (int i = 0; i < 2; i++) {
        pa[i] = *reinterpret_cast<const float4*>(A + aoffv[i] + kqv[i]);
        pw[i] = *reinterpret_cast<const float4*>(W + woffv[i] + kqv[i]);
    }

    for (int kt = 0; kt < K; kt += 16) {
#pragma unroll
        for (int i = 0; i < 2; i++) {
            int k = kqv[i], rr = rrv[i];
            As[k+0][rr]=pa[i].x; As[k+1][rr]=pa[i].y; As[k+2][rr]=pa[i].z; As[k+3][rr]=pa[i].w;
            Ws[k+0][rr]=pw[i].x; Ws[k+1][rr]=pw[i].y; Ws[k+2][rr]=pw[i].z; Ws[k+3][rr]=pw[i].w;
        }
        __syncthreads();
        if (kt + 16 < K) {
#pragma unroll
            for (int i = 0; i < 2; i++) {
                pa[i] = *reinterpret_cast<const float4*>(A + aoffv[i] + kt + 16 + kqv[i]);
                pw[i] = *reinterpret_cast<const float4*>(W + woffv[i] + kt + 16 + kqv[i]);
            }
        }
#pragma unroll
        for (int k = 0; k < 16; k++) {
            float a[8];
            *reinterpret_cast<float4*>(&a[0]) = *reinterpret_cast<const float4*>(&As[k][tm << 3]);
            *reinterpret_cast<float4*>(&a[4]) = *reinterpret_cast<const float4*>(&As[k][(tm << 3) + 4]);
            ull w2[4];
#pragma unroll
            for (int g = 0; g < 4; g++)
                w2[g] = *reinterpret_cast<const ull*>(&Ws[k][(g << 5) + (tn << 1)]);
#pragma unroll
            for (int i = 0; i < 8; i++) {
                ull ad = dup2(a[i]);
#pragma unroll
                for (int g = 0; g < 4; g++) acc[i][g] = ffma2(ad, w2[g], acc[i][g]);
            }
        }
        __syncthreads();
    }

    const int n = n0 + (tn << 1);
    float bv0[4], bv1[4];
#pragma unroll
    for (int g = 0; g < 4; g++) {
        bv0[g] = b1[(g << 8) + n]     + b2[(g << 8) + n];
        bv1[g] = b1[(g << 8) + n + 1] + b2[(g << 8) + n + 1];
    }
    float4* out4 = reinterpret_cast<float4*>(out);
#pragma unroll
    for (int i = 0; i < 8; i++) {
        int m = m0 + (tm << 3) + i;
        float2 q0 = unpk(acc[i][0]), q1 = unpk(acc[i][1]);
        float2 q2 = unpk(acc[i][2]), q3 = unpk(acc[i][3]);
        out4[(size_t)m * 256 + n]     = make_float4(q0.x+bv0[0], q1.x+bv0[1], q2.x+bv0[2], q3.x+bv0[3]);
        out4[(size_t)m * 256 + n + 1] = make_float4(q0.y+bv1[0], q1.y+bv1[1], q2.y+bv1[2], q3.y+bv1[3]);
    }
}

// ---- persistent LSTM recurrence ----
// 128 CTAs = 16 batch-groups x 8 n-groups. Warp kg owns k-slice [32kg,32kg+32),
// produced by exactly CTA ni==kg of the same group -> warp polls ONLY that counter.
__global__ void __launch_bounds__(256, 1) rec_kernel(
    const float* __restrict__ xg, const float* __restrict__ Whh,
    float* __restrict__ hist)
{
    extern __shared__ float sm[];
    float* Wsh = sm;            // [k][nn*4+g]  32768 floats
    float* hsh = Wsh + 32768;   // 8 warps x [16][36] = 4608
    float* red = hsh + 4608;    // [kg][cell][4] = 16384

    const int bi = blockIdx.x >> 3, ni = blockIdx.x & 7;
    const int b0 = bi << 4, n0 = ni << 5;
    const int tid = threadIdx.x;
    const int kg  = tid >> 5;
    const int cid = tid & 31;
    const int bb  = (cid >> 4) << 3;
    const int pn  = cid & 15;

    // Wsh[k][nn*4+g] = Whh[g*256 + n0 + nn][k]
    for (int idx = tid; idx < 8192; idx += 256) {
        int kq = idx & 63, c = idx >> 6;
        int nn = c >> 2, g = c & 3;
        float4 v = *reinterpret_cast<const float4*>(
            Whh + (size_t)((g << 8) + n0 + nn) * HIDN + (kq << 2));
        int k = kq << 2;
        Wsh[(k+0)*128+c]=v.x; Wsh[(k+1)*128+c]=v.y; Wsh[(k+2)*128+c]=v.z; Wsh[(k+3)*128+c]=v.w;
    }
    __syncthreads();

    const int p0i = tid << 1;
    const int eb  = p0i >> 5, enn = p0i & 31;

    const unsigned* prodcnt = g_bar + (bi << 3) + kg;   // this warp's sole producer
    unsigned* mycnt = g_bar + (bi << 3) + ni;

    float* hshW = hsh + kg * 576;
    // precomputed cp.async dst addresses (4 per lane)
    uint32_t stg_dst[4];
    int      stg_boff[4];
#pragma unroll
    for (int i = 0; i < 4; i++) {
        int f  = cid + (i << 5);
        int b  = f >> 3, c4 = (f & 7) << 2;
        stg_dst[i]  = smem_u32(hshW + b * 36 + c4);
        stg_boff[i] = (b << 8) + c4;
    }

    const float4* xg4 = reinterpret_cast<const float4*>(xg);
    float creg[2] = {0.f, 0.f};

    for (int t = 0; t < TSEQ; t++) {
        // prefetch gate quads (independent of h)
        size_t xi = ((size_t)t * BSZ + b0 + eb) * 256 + n0 + enn;
        ulonglong2 xq0 = *reinterpret_cast<const ulonglong2*>(&xg4[xi]);
        ulonglong2 xq1 = *reinterpret_cast<const ulonglong2*>(&xg4[xi + 1]);

        ull acc2[8][4];
#pragma unroll
        for (int i = 0; i < 8; i++)
#pragma unroll
            for (int j = 0; j < 4; j++) acc2[i][j] = 0ull;

        if (t > 0) {
            // wait only on this warp's producer having finished step t-1
            const unsigned tgt = (unsigned)t;
            while (ld_acq(prodcnt) < tgt) {}

            // stage own k-slice via cp.async: 16 batches x 32 k (warp-private)
            const float* hp = hist + ((size_t)(t - 1) * BSZ + b0) * HIDN + (kg << 5);
#pragma unroll
            for (int i = 0; i < 4; i++)
                cp_async16(stg_dst[i], hp + stg_boff[i]);
            cp_async_wait_all();
            __syncwarp();

            const float* hpL = hshW + bb * 36;
            const float* wp  = Wsh + ((kg << 5) * 128) + (pn << 3);
#pragma unroll 8
            for (int k = 0; k < 32; k++) {
                ulonglong2 wa = *reinterpret_cast<const ulonglong2*>(wp);
                ulonglong2 wb = *reinterpret_cast<const ulonglong2*>(wp + 4);
                wp += 128;
#pragma unroll
                for (int i = 0; i < 8; i++) {
                    ull hd = dup2(hpL[i * 36 + k]);
                    acc2[i][0] = ffma2(hd, wa.x, acc2[i][0]);
                    acc2[i][1] = ffma2(hd, wa.y, acc2[i][1]);
                    acc2[i][2] = ffma2(hd, wb.x, acc2[i][2]);
                    acc2[i][3] = ffma2(hd, wb.y, acc2[i][3]);
                }
            }
        }

        // gate-quad partials: red[kg][cell][4]
#pragma unroll
        for (int i = 0; i < 8; i++) {
            float* rp = red + (kg << 11) + (((bb + i) << 5) + (pn << 1)) * 4;
            *reinterpret_cast<ulonglong2*>(rp)     = make_ulonglong2(acc2[i][0], acc2[i][1]);
            *reinterpret_cast<ulonglong2*>(rp + 4) = make_ulonglong2(acc2[i][2], acc2[i][3]);
        }
        __syncthreads();

        // epilogue: packed quad reduction + activations, c in registers
        float* ho = hist + ((size_t)t * BSZ + b0 + eb) * HIDN + n0 + enn;
        float hout[2];
#pragma unroll
        for (int pp = 0; pp < 2; pp++) {
            int cell = (eb << 5) + enn + pp;
            ull s01 = pp ? xq1.x : xq0.x;
            ull s23 = pp ? xq1.y : xq0.y;
            const float* rb = red + cell * 4;
#pragma unroll
            for (int s = 0; s < 8; s++) {
                ulonglong2 r = *reinterpret_cast<const ulonglong2*>(rb + (s << 11));
                s01 = add2(s01, r.x);
                s23 = add2(s23, r.y);
            }
            float2 g01 = unpk(s01), g23 = unpk(s23);
            float cn = sigm(g01.y) * creg[pp] + sigm(g01.x) * ftanh(g23.x);
            creg[pp] = cn;
            hout[pp] = sigm(g23.y) * ftanh(cn);
        }
        *reinterpret_cast<float2*>(ho) = make_float2(hout[0], hout[1]);

        __syncthreads();                              // all h stores + red reads done
        if (tid == 0) red_rel_add(mycnt, 1u);         // publish step t (own counter)
    }
}

// ---- head ----
__global__ void head_kernel(const float* __restrict__ Wh, const float* __restrict__ bh,
                            float* __restrict__ out)
{
    __shared__ float rs[8];
    int b = blockIdx.x, tid = threadIdx.x;
    float v = g_hist1[((size_t)(TSEQ - 1) * BSZ + b) * HIDN + tid] * Wh[tid];
#pragma unroll
    for (int o = 16; o > 0; o >>= 1) v += __shfl_down_sync(0xffffffffu, v, o);
    if ((tid & 31) == 0) rs[tid >> 5] = v;
    __syncthreads();
    if (tid < 8) {
        float s = rs[tid];
#pragma unroll
        for (int o = 4; o > 0; o >>= 1) s += __shfl_down_sync(0xffu, s, o);
        if (tid == 0) out[b] = s + bh[0];
    }
}

extern "C" void kernel_launch(void* const* d_in, const int* in_sizes, int n_in,
                              void* d_out, int out_size)
{
    const float* x      = (const float*)d_in[0];
    const float* W_ih0  = (const float*)d_in[1];
    const float* W_hh0  = (const float*)d_in[2];
    const float* b_ih0  = (const float*)d_in[3];
    const float* b_hh0  = (const float*)d_in[4];
    const float* W_ih1  = (const float*)d_in[5];
    const float* W_hh1  = (const float*)d_in[6];
    const float* b_ih1  = (const float*)d_in[7];
    const float* b_hh1  = (const float*)d_in[8];
    const float* W_head = (const float*)d_in[9];
    const float* b_head = (const float*)d_in[10];
    float* out = (float*)d_out;

    void *pxg, *ph0, *ph1;
    cudaGetSymbolAddress(&pxg, g_xg);
    cudaGetSymbolAddress(&ph0, g_hist0);
    cudaGetSymbolAddress(&ph1, g_hist1);
    float* xg = (float*)pxg; float* h0 = (float*)ph0; float* h1 = (float*)ph1;

    const int SMEM = 53760 * 4;   // 215040 B
    cudaFuncSetAttribute(rec_kernel, cudaFuncAttributeMaxDynamicSharedMemorySize, SMEM);

    dim3 gg(1024, 8);
    gemm_xg<64,  true ><<<gg, 256>>>(x,  W_ih0, b_ih0, b_hh0, xg);
    reset_bar<<<1, 128>>>();
    rec_kernel<<<128, 256, SMEM>>>(xg, W_hh0, h0);
    gemm_xg<256, false><<<gg, 256>>>(h0, W_ih1, b_ih1, b_hh1, xg);
    reset_bar<<<1, 128>>>();
    rec_kernel<<<128, 256, SMEM>>>(xg, W_hh1, h1);
    head_kernel<<<256, 256>>>(W_head, b_head, out);
}

// round 14
// speedup vs baseline: 1.5437x; 1.1931x over previous
#include <cuda_runtime.h>
#include <cuda_bf16.h>
#include <cstdint>

#define BSZ  256
#define TSEQ 512
#define HIDN 256

typedef unsigned long long ull;

// ---- static scratch ----
// xg layout: [t][b][n][4] (gate quads)
__device__ float g_xg[(size_t)TSEQ * BSZ * 1024];
__device__ float g_hist0[(size_t)TSEQ * BSZ * HIDN];
__device__ float g_hist1[(size_t)TSEQ * BSZ * HIDN];
__device__ unsigned g_bar[128];   // [batch-group][producer ni]

__global__ void reset_bar() { if (threadIdx.x < 128) g_bar[threadIdx.x] = 0u; }

__device__ __forceinline__ float sigm(float x) { return 1.f / (1.f + __expf(-x)); }
__device__ __forceinline__ float ftanh(float x) {
    float e = __expf(-2.f * fabsf(x));
    return copysignf((1.f - e) / (1.f + e), x);
}

// ---- packed fp32x2 (Blackwell) ----
__device__ __forceinline__ ull ffma2(ull a, ull b, ull c) {
    ull d; asm("fma.rn.f32x2 %0, %1, %2, %3;" : "=l"(d) : "l"(a), "l"(b), "l"(c)); return d;
}
__device__ __forceinline__ ull add2(ull a, ull b) {
    ull d; asm("add.rn.f32x2 %0, %1, %2;" : "=l"(d) : "l"(a), "l"(b)); return d;
}
__device__ __forceinline__ ull dup2(float x) {
    ull r; asm("mov.b64 %0, {%1, %1};" : "=l"(r) : "f"(x)); return r;
}
__device__ __forceinline__ float2 unpk(ull v) {
    float2 f; asm("mov.b64 {%0, %1}, %2;" : "=f"(f.x), "=f"(f.y) : "l"(v)); return f;
}

// ---- scoped sync ----
__device__ __forceinline__ unsigned ld_acq(const unsigned* p) {
    unsigned v; asm volatile("ld.acquire.gpu.global.b32 %0, [%1];" : "=r"(v) : "l"(p)); return v;
}
__device__ __forceinline__ void red_rel_add(unsigned* p, unsigned v) {
    asm volatile("red.release.gpu.global.add.u32 [%0], %1;" :: "l"(p), "r"(v) : "memory");
}

// ---- smem helpers ----
__device__ __forceinline__ uint32_t smem_u32(const void* p) {
    uint32_t a;
    asm("{ .reg .u64 t; cvta.to.shared.u64 t, %1; cvt.u32.u64 %0, t; }" : "=r"(a) : "l"(p));
    return a;
}

// ---- tensor core primitives ----
__device__ __forceinline__ void ldsm_x4(uint32_t* r, uint32_t addr) {
    asm volatile("ldmatrix.sync.aligned.m8n8.x4.shared.b16 {%0,%1,%2,%3}, [%4];"
        : "=r"(r[0]), "=r"(r[1]), "=r"(r[2]), "=r"(r[3]) : "r"(addr));
}
__device__ __forceinline__ void mma_bf16(float* c, const uint32_t* a, uint32_t b0, uint32_t b1) {
    asm volatile("mma.sync.aligned.m16n8k16.row.col.f32.bf16.bf16.f32 "
        "{%0,%1,%2,%3}, {%4,%5,%6,%7}, {%8,%9}, {%0,%1,%2,%3};"
        : "+f"(c[0]), "+f"(c[1]), "+f"(c[2]), "+f"(c[3])
        : "r"(a[0]), "r"(a[1]), "r"(a[2]), "r"(a[3]), "r"(b0), "r"(b1));
}

// ---- GEMM: xg[m*256 + n] (float4 gate quad) = A_row(m).W[g*256+n] + biases ----
template<int K, bool XMODE>
__global__ void __launch_bounds__(256, 2) gemm_xg(
    const float* __restrict__ A, const float* __restrict__ W,
    const float* __restrict__ b1, const float* __restrict__ b2,
    float* __restrict__ out)
{
    __shared__ float As[16][132];
    __shared__ float Ws[16][132];
    const int m0 = blockIdx.x * 128, n0 = blockIdx.y * 32;
    const int tid = threadIdx.x;
    const int tm = tid >> 4, tn = tid & 15;

    int rrv[2], kqv[2];
#pragma unroll
    for (int i = 0; i < 2; i++) { int idx = tid + (i << 8); rrv[i] = idx >> 2; kqv[i] = (idx & 3) << 2; }
    size_t aoffv[2], woffv[2];
#pragma unroll
    for (int i = 0; i < 2; i++) {
        int row = m0 + rrv[i];
        if (XMODE) aoffv[i] = ((size_t)(row & 255) * TSEQ + (row >> 8)) * K;
        else       aoffv[i] = (size_t)row * K;
        int wrow = ((rrv[i] >> 5) << 8) + n0 + (rrv[i] & 31);
        woffv[i] = (size_t)wrow * K;
    }

    ull acc[8][4];
#pragma unroll
    for (int i = 0; i < 8; i++)
#pragma unroll
        for (int j = 0; j < 4; j++) acc[i][j] = 0ull;

    float4 pa[2], pw[2];
#pragma unroll
    for (int i = 0; i < 2; i++) {
        pa[i] = *reinterpret_cast<const float4*>(A + aoffv[i] + kqv[i]);
        pw[i] = *reinterpret_cast<const float4*>(W + woffv[i] + kqv[i]);
    }

    for (int kt = 0; kt < K; kt += 16) {
#pragma unroll
        for (int i = 0; i < 2; i++) {
            int k = kqv[i], rr = rrv[i];
            As[k+0][rr]=pa[i].x; As[k+1][rr]=pa[i].y; As[k+2][rr]=pa[i].z; As[k+3][rr]=pa[i].w;
            Ws[k+0][rr]=pw[i].x; Ws[k+1][rr]=pw[i].y; Ws[k+2][rr]=pw[i].z; Ws[k+3][rr]=pw[i].w;
        }
        __syncthreads();
        if (kt + 16 < K) {
#pragma unroll
            for (int i = 0; i < 2; i++) {
                pa[i] = *reinterpret_cast<const float4*>(A + aoffv[i] + kt + 16 + kqv[i]);
                pw[i] = *reinterpret_cast<const float4*>(W + woffv[i] + kt + 16 + kqv[i]);
            }
        }
#pragma unroll
        for (int k = 0; k < 16; k++) {
            float a[8];
            *reinterpret_cast<float4*>(&a[0]) = *reinterpret_cast<const float4*>(&As[k][tm << 3]);
            *reinterpret_cast<float4*>(&a[4]) = *reinterpret_cast<const float4*>(&As[k][(tm << 3) + 4]);
            ull w2[4];
#pragma unroll
            for (int g = 0; g < 4; g++)
                w2[g] = *reinterpret_cast<const ull*>(&Ws[k][(g << 5) + (tn << 1)]);
#pragma unroll
            for (int i = 0; i < 8; i++) {
                ull ad = dup2(a[i]);
#pragma unroll
                for (int g = 0; g < 4; g++) acc[i][g] = ffma2(ad, w2[g], acc[i][g]);
            }
        }
        __syncthreads();
    }

    const int n = n0 + (tn << 1);
    float bv0[4], bv1[4];
#pragma unroll
    for (int g = 0; g < 4; g++) {
        bv0[g] = b1[(g << 8) + n]     + b2[(g << 8) + n];
        bv1[g] = b1[(g << 8) + n + 1] + b2[(g << 8) + n + 1];
    }
    float4* out4 = reinterpret_cast<float4*>(out);
#pragma unroll
    for (int i = 0; i < 8; i++) {
        int m = m0 + (tm << 3) + i;
        float2 q0 = unpk(acc[i][0]), q1 = unpk(acc[i][1]);
        float2 q2 = unpk(acc[i][2]), q3 = unpk(acc[i][3]);
        out4[(size_t)m * 256 + n]     = make_float4(q0.x+bv0[0], q1.x+bv0[1], q2.x+bv0[2], q3.x+bv0[3]);
        out4[(size_t)m * 256 + n + 1] = make_float4(q0.y+bv1[0], q1.y+bv1[1], q2.y+bv1[2], q3.y+bv1[3]);
    }
}

// ---- persistent LSTM recurrence, split-bf16 tensor-core dot ----
// 128 CTAs = 16 batch-groups x 8 n-groups. Warp kg owns k-slice [32kg,32kg+32),
// produced by CTA ni==kg of the same group -> warp polls only that counter.
// h stays fp32 in global; consumers split hi/lo in-register during staging.
// Warp dot: M=16 batches x N=128 gate-cols x K=32 via mma m16n8k16 bf16,
// 3-term split (hi*Whi + lo*Whi + hi*Wlo).
// SMEM map (bytes): Whi [0,67584) | Wlo [67584,135168) | stg [135168,155648)
//                   red [155648,221184)  -- red = 8 warps x 2048 floats (64 KB)
__global__ void __launch_bounds__(256, 1) rec_kernel(
    const float* __restrict__ xg, const float* __restrict__ Whh,
    float* __restrict__ hist)
{
    extern __shared__ char smc[];
    __nv_bfloat16* Whi = reinterpret_cast<__nv_bfloat16*>(smc);   // [128 c][264 k]
    __nv_bfloat16* Wlo = Whi + 128 * 264;
    float* red = reinterpret_cast<float*>(smc + 155648);          // [kg][b*128+c] fp32, 64 KB

    const int bi = blockIdx.x >> 3, ni = blockIdx.x & 7;
    const int b0 = bi << 4, n0 = ni << 5;
    const int tid = threadIdx.x;
    const int kg  = tid >> 5;
    const int cid = tid & 31;

    // ---- split W_hh slice into bf16 hi/lo planes: W*[c][k], c = nn*4+g ----
    for (int idx = tid; idx < 128 * 256; idx += 256) {
        int c = idx >> 8, k = idx & 255;
        int row = ((c & 3) << 8) + n0 + (c >> 2);
        float w = Whh[(size_t)row * 256 + k];
        __nv_bfloat16 h = __float2bfloat16(w);
        __nv_bfloat16 l = __float2bfloat16(w - __bfloat162float(h));
        Whi[c * 264 + k] = h;
        Wlo[c * 264 + k] = l;
    }
    __syncthreads();

    // epilogue cells
    const int p0i = tid << 1;
    const int eb  = p0i >> 5, enn = p0i & 31;

    const unsigned* prodcnt = g_bar + (bi << 3) + kg;
    unsigned* mycnt = g_bar + (bi << 3) + ni;

    // warp-private staging region: hi[16][40] + lo[16][40] bf16
    char* stgW = smc + 135168 + kg * 2560;
    const uint32_t stg_b = smem_u32(stgW);

    // ldmatrix A addresses [plane][k-chunk]
    uint32_t aaddr[2][2];
    {
        int arow = cid & 15;
        int acolB = ((cid >> 4) << 3) * 2;    // 0 or 16 bytes
#pragma unroll
        for (int p = 0; p < 2; p++)
#pragma unroll
            for (int q = 0; q < 2; q++)
                aaddr[p][q] = stg_b + p * 1280 + arow * 80 + acolB + q * 32;
    }
    // ldmatrix B base (j=0)
    const uint32_t wbB = smem_u32(Whi);
    const uint32_t baddr0 = wbB + (((cid & 7) * 264) + (kg << 5) + ((cid >> 3) << 3)) * 2;
    const uint32_t BLO = 128 * 264 * 2;

    // D-fragment store base
    const int dg = cid >> 2, dtq = cid & 3;
    float* redw = red + (kg << 11) + (dg << 7) + (dtq << 1);

    const float4* xg4 = reinterpret_cast<const float4*>(xg);
    float creg[2] = {0.f, 0.f};

    for (int t = 0; t < TSEQ; t++) {
        // prefetch gate quads (independent of h)
        size_t xi = ((size_t)t * BSZ + b0 + eb) * 256 + n0 + enn;
        ulonglong2 xq0 = *reinterpret_cast<const ulonglong2*>(&xg4[xi]);
        ulonglong2 xq1 = *reinterpret_cast<const ulonglong2*>(&xg4[xi + 1]);

        if (t > 0) {
            const unsigned tgt = (unsigned)t;
            while (ld_acq(prodcnt) < tgt) {}

            // stage fp32 h(t-1) k-slice, split to bf16 hi/lo planes (warp-private)
            const float* hp = hist + ((size_t)(t - 1) * BSZ + b0) * HIDN + (kg << 5);
#pragma unroll
            for (int i = 0; i < 4; i++) {
                int f  = cid + (i << 5);
                int br = f >> 3, c4 = (f & 7) << 2;
                float4 v = *reinterpret_cast<const float4*>(hp + (br << 8) + c4);
                __nv_bfloat162 ha = __floats2bfloat162_rn(v.x, v.y);
                __nv_bfloat162 hb = __floats2bfloat162_rn(v.z, v.w);
                float lx = v.x - __bfloat162float(ha.x);
                float ly = v.y - __bfloat162float(ha.y);
                float lz = v.z - __bfloat162float(hb.x);
                float lw = v.w - __bfloat162float(hb.y);
                __nv_bfloat162 la = __floats2bfloat162_rn(lx, ly);
                __nv_bfloat162 lb = __floats2bfloat162_rn(lz, lw);
                char* dst = stgW + br * 80 + (c4 << 1);
                *reinterpret_cast<__nv_bfloat162*>(dst)        = ha;
                *reinterpret_cast<__nv_bfloat162*>(dst + 4)    = hb;
                *reinterpret_cast<__nv_bfloat162*>(dst + 1280) = la;
                *reinterpret_cast<__nv_bfloat162*>(dst + 1284) = lb;
            }
            __syncwarp();

            // A fragments (hi/lo planes, k 0-15 and 16-31)
            uint32_t Ah[2][4], Al[2][4];
            ldsm_x4(Ah[0], aaddr[0][0]); ldsm_x4(Ah[1], aaddr[0][1]);
            ldsm_x4(Al[0], aaddr[1][0]); ldsm_x4(Al[1], aaddr[1][1]);

            uint32_t bh = baddr0;
#pragma unroll
            for (int j = 0; j < 16; j += 2) {
                uint32_t B0h[4], B0l[4], B1h[4], B1l[4];
                ldsm_x4(B0h, bh);        ldsm_x4(B0l, bh + BLO);
                ldsm_x4(B1h, bh + 4224); ldsm_x4(B1l, bh + 4224 + BLO);
                bh += 8448;
                float c0[4] = {0.f,0.f,0.f,0.f}, c1[4] = {0.f,0.f,0.f,0.f};
                mma_bf16(c0, Ah[0], B0h[0], B0h[1]); mma_bf16(c1, Ah[0], B1h[0], B1h[1]);
                mma_bf16(c0, Ah[1], B0h[2], B0h[3]); mma_bf16(c1, Ah[1], B1h[2], B1h[3]);
                mma_bf16(c0, Al[0], B0h[0], B0h[1]); mma_bf16(c1, Al[0], B1h[0], B1h[1]);
                mma_bf16(c0, Al[1], B0h[2], B0h[3]); mma_bf16(c1, Al[1], B1h[2], B1h[3]);
                mma_bf16(c0, Ah[0], B0l[0], B0l[1]); mma_bf16(c1, Ah[0], B1l[0], B1l[1]);
                mma_bf16(c0, Ah[1], B0l[2], B0l[3]); mma_bf16(c1, Ah[1], B1l[2], B1l[3]);
                *reinterpret_cast<float2*>(redw + (j << 3))          = make_float2(c0[0], c0[1]);
                *reinterpret_cast<float2*>(redw + (j << 3) + 1024)   = make_float2(c0[2], c0[3]);
                *reinterpret_cast<float2*>(redw + (j << 3) + 8)      = make_float2(c1[0], c1[1]);
                *reinterpret_cast<float2*>(redw + (j << 3) + 8+1024) = make_float2(c1[2], c1[3]);
            }
        } else {
            float4 z = make_float4(0.f, 0.f, 0.f, 0.f);
            for (int i = cid; i < 512; i += 32)
                *reinterpret_cast<float4*>(red + (kg << 11) + (i << 2)) = z;
        }
        __syncthreads();

        // epilogue: packed quad reduction + activations, c-state in registers
        float* ho = hist + ((size_t)t * BSZ + b0 + eb) * HIDN + n0 + enn;
        float hout[2];
#pragma unroll
        for (int pp = 0; pp < 2; pp++) {
            int cell = (eb << 5) + enn + pp;
            ull s01 = pp ? xq1.x : xq0.x;
            ull s23 = pp ? xq1.y : xq0.y;
            const float* rb = red + (cell << 2);
#pragma unroll
            for (int s = 0; s < 8; s++) {
                ulonglong2 r = *reinterpret_cast<const ulonglong2*>(rb + (s << 11));
                s01 = add2(s01, r.x);
                s23 = add2(s23, r.y);
            }
            float2 g01 = unpk(s01), g23 = unpk(s23);
            float cn = sigm(g01.y) * creg[pp] + sigm(g01.x) * ftanh(g23.x);
            creg[pp] = cn;
            hout[pp] = sigm(g23.y) * ftanh(cn);
        }
        *reinterpret_cast<float2*>(ho) = make_float2(hout[0], hout[1]);

        __syncthreads();
        if (tid == 0) red_rel_add(mycnt, 1u);
    }
}

// ---- head ----
__global__ void head_kernel(const float* __restrict__ Wh, const float* __restrict__ bh,
                            float* __restrict__ out)
{
    __shared__ float rs[8];
    int b = blockIdx.x, tid = threadIdx.x;
    float v = g_hist1[((size_t)(TSEQ - 1) * BSZ + b) * HIDN + tid] * Wh[tid];
#pragma unroll
    for (int o = 16; o > 0; o >>= 1) v += __shfl_down_sync(0xffffffffu, v, o);
    if ((tid & 31) == 0) rs[tid >> 5] = v;
    __syncthreads();
    if (tid < 8) {
        float s = rs[tid];
#pragma unroll
        for (int o = 4; o > 0; o >>= 1) s += __shfl_down_sync(0xffu, s, o);
        if (tid == 0) out[b] = s + bh[0];
    }
}

extern "C" void kernel_launch(void* const* d_in, const int* in_sizes, int n_in,
                              void* d_out, int out_size)
{
    const float* x      = (const float*)d_in[0];
    const float* W_ih0  = (const float*)d_in[1];
    const float* W_hh0  = (const float*)d_in[2];
    const float* b_ih0  = (const float*)d_in[3];
    const float* b_hh0  = (const float*)d_in[4];
    const float* W_ih1  = (const float*)d_in[5];
    const float* W_hh1  = (const float*)d_in[6];
    const float* b_ih1  = (const float*)d_in[7];
    const float* b_hh1  = (const float*)d_in[8];
    const float* W_head = (const float*)d_in[9];
    const float* b_head = (const float*)d_in[10];
    float* out = (float*)d_out;

    void *pxg, *ph0, *ph1;
    cudaGetSymbolAddress(&pxg, g_xg);
    cudaGetSymbolAddress(&ph0, g_hist0);
    cudaGetSymbolAddress(&ph1, g_hist1);
    float* xg = (float*)pxg; float* h0 = (float*)ph0; float* h1 = (float*)ph1;

    const int SMEM = 221184;   // W planes 132KB + staging 20KB + red 64KB
    cudaFuncSetAttribute(rec_kernel, cudaFuncAttributeMaxDynamicSharedMemorySize, SMEM);

    dim3 gg(1024, 8);
    gemm_xg<64,  true ><<<gg, 256>>>(x,  W_ih0, b_ih0, b_hh0, xg);
    reset_bar<<<1, 128>>>();
    rec_kernel<<<128, 256, SMEM>>>(xg, W_hh0, h0);
    gemm_xg<256, false><<<gg, 256>>>(h0, W_ih1, b_ih1, b_hh1, xg);
    reset_bar<<<1, 128>>>();
    rec_kernel<<<128, 256, SMEM>>>(xg, W_hh1, h1);
    head_kernel<<<256, 256>>>(W_head, b_head, out);
}

// round 15
// speedup vs baseline: 1.6913x; 1.0956x over previous
#include <cuda_runtime.h>
#include <cuda_bf16.h>
#include <cstdint>

#define BSZ  256
#define TSEQ 512
#define HIDN 256

typedef unsigned long long ull;

// ---- static scratch ----
// xg layout: [t][b][n][4] (gate quads)
__device__ float g_xg[(size_t)TSEQ * BSZ * 1024];
__device__ float g_hist0[(size_t)TSEQ * BSZ * HIDN];
__device__ float g_hist1[(size_t)TSEQ * BSZ * HIDN];
__device__ unsigned g_bar[128];   // [batch-group][producer ni]

__global__ void reset_bar() { if (threadIdx.x < 128) g_bar[threadIdx.x] = 0u; }

__device__ __forceinline__ float sigm(float x) { return 1.f / (1.f + __expf(-x)); }
__device__ __forceinline__ float ftanh(float x) {
    float e = __expf(-2.f * fabsf(x));
    return copysignf((1.f - e) / (1.f + e), x);
}

__device__ __forceinline__ ull add2(ull a, ull b) {
    ull d; asm("add.rn.f32x2 %0, %1, %2;" : "=l"(d) : "l"(a), "l"(b)); return d;
}
__device__ __forceinline__ float2 unpk(ull v) {
    float2 f; asm("mov.b64 {%0, %1}, %2;" : "=f"(f.x), "=f"(f.y) : "l"(v)); return f;
}

// ---- scoped sync ----
__device__ __forceinline__ unsigned ld_acq(const unsigned* p) {
    unsigned v; asm volatile("ld.acquire.gpu.global.b32 %0, [%1];" : "=r"(v) : "l"(p)); return v;
}
__device__ __forceinline__ void red_rel_add(unsigned* p, unsigned v) {
    asm volatile("red.release.gpu.global.add.u32 [%0], %1;" :: "l"(p), "r"(v) : "memory");
}

// ---- smem helpers ----
__device__ __forceinline__ uint32_t smem_u32(const void* p) {
    uint32_t a;
    asm("{ .reg .u64 t; cvta.to.shared.u64 t, %1; cvt.u32.u64 %0, t; }" : "=r"(a) : "l"(p));
    return a;
}

// ---- tensor core primitives ----
__device__ __forceinline__ void ldsm_x4(uint32_t* r, uint32_t addr) {
    asm volatile("ldmatrix.sync.aligned.m8n8.x4.shared.b16 {%0,%1,%2,%3}, [%4];"
        : "=r"(r[0]), "=r"(r[1]), "=r"(r[2]), "=r"(r[3]) : "r"(addr));
}
__device__ __forceinline__ void mma_bf16(float* c, const uint32_t* a, uint32_t b0, uint32_t b1) {
    asm volatile("mma.sync.aligned.m16n8k16.row.col.f32.bf16.bf16.f32 "
        "{%0,%1,%2,%3}, {%4,%5,%6,%7}, {%8,%9}, {%0,%1,%2,%3};"
        : "+f"(c[0]), "+f"(c[1]), "+f"(c[2]), "+f"(c[3])
        : "r"(a[0]), "r"(a[1]), "r"(a[2]), "r"(a[3]), "r"(b0), "r"(b1));
}

// =======================================================================
// GEMM (split-bf16 HMMA): xg[m][n] gate quads = A_row(m).W[g*256+n] + b
// Block: 128 m x (32 n x 4 gates = 128 c-rows).  grid (M/128, 8).
// Warp wid: rows [m0+16wid, +16), all 128 c-cols, K accumulated in regs.
// SMEM (bytes): Ahi[0,18432) Alo[18432) Whi[36864) Wlo[55296) bsh[73728,74240)
// bf16 tiles: [128][72] pitch (144B rows, conflict-staggered for ldmatrix).
// =======================================================================
template<int K, bool XMODE>
__global__ void __launch_bounds__(256) gemm_bf16(
    const float* __restrict__ A, const float* __restrict__ W,
    const float* __restrict__ b1, const float* __restrict__ b2,
    float* __restrict__ out)
{
    extern __shared__ char smg[];
    const int PLANE = 18432;
    __nv_bfloat16* Ahi = reinterpret_cast<__nv_bfloat16*>(smg);
    __nv_bfloat16* Alo = reinterpret_cast<__nv_bfloat16*>(smg + 18432);
    __nv_bfloat16* Whi = reinterpret_cast<__nv_bfloat16*>(smg + 36864);
    __nv_bfloat16* Wlo = reinterpret_cast<__nv_bfloat16*>(smg + 55296);
    float* bsh = reinterpret_cast<float*>(smg + 73728);

    const int m0 = blockIdx.x * 128, n0 = blockIdx.y * 32;
    const int tid = threadIdx.x;
    const int wid = tid >> 5, cid = tid & 31;

    if (tid < 128) {
        int row = ((tid & 3) << 8) + n0 + (tid >> 2);
        bsh[tid] = b1[row] + b2[row];
    }

    float c[16][4];
#pragma unroll
    for (int j = 0; j < 16; j++)
#pragma unroll
        for (int q = 0; q < 4; q++) c[j][q] = 0.f;

    // ldmatrix addresses
    const uint32_t a_hi = smem_u32(Ahi) + ((wid << 4) + (cid & 15)) * 144 + ((cid >> 4) << 4);
    const uint32_t a_lo = a_hi + PLANE;
    const uint32_t b_hi = smem_u32(Whi) + (cid & 7) * 144 + ((cid >> 3) << 4);

    for (int kt = 0; kt < K; kt += 64) {
        __syncthreads();   // previous chunk fully consumed
        // ---- stage A chunk: 128 rows x 64 k, split hi/lo ----
#pragma unroll
        for (int i = 0; i < 8; i++) {
            int idx = tid + (i << 8);
            int r = idx >> 4, k4 = (idx & 15) << 2;
            int row = m0 + r;
            size_t aoff;
            if (XMODE) aoff = ((size_t)(row & 255) * TSEQ + (row >> 8)) * K;
            else       aoff = (size_t)row * K;
            float4 v = *reinterpret_cast<const float4*>(A + aoff + kt + k4);
            __nv_bfloat162 ha = __floats2bfloat162_rn(v.x, v.y);
            __nv_bfloat162 hb = __floats2bfloat162_rn(v.z, v.w);
            __nv_bfloat162 la = __floats2bfloat162_rn(v.x - __bfloat162float(ha.x),
                                                      v.y - __bfloat162float(ha.y));
            __nv_bfloat162 lb = __floats2bfloat162_rn(v.z - __bfloat162float(hb.x),
                                                      v.w - __bfloat162float(hb.y));
            int o = r * 72 + k4;
            *reinterpret_cast<__nv_bfloat162*>(Ahi + o)     = ha;
            *reinterpret_cast<__nv_bfloat162*>(Ahi + o + 2) = hb;
            *reinterpret_cast<__nv_bfloat162*>(Alo + o)     = la;
            *reinterpret_cast<__nv_bfloat162*>(Alo + o + 2) = lb;
        }
        // ---- stage W chunk: 128 c-rows x 64 k, split hi/lo ----
#pragma unroll
        for (int i = 0; i < 8; i++) {
            int idx = tid + (i << 8);
            int r = idx >> 4, k4 = (idx & 15) << 2;
            int wrow = ((r & 3) << 8) + n0 + (r >> 2);
            float4 v = *reinterpret_cast<const float4*>(W + (size_t)wrow * K + kt + k4);
            __nv_bfloat162 ha = __floats2bfloat162_rn(v.x, v.y);
            __nv_bfloat162 hb = __floats2bfloat162_rn(v.z, v.w);
            __nv_bfloat162 la = __floats2bfloat162_rn(v.x - __bfloat162float(ha.x),
                                                      v.y - __bfloat162float(ha.y));
            __nv_bfloat162 lb = __floats2bfloat162_rn(v.z - __bfloat162float(hb.x),
                                                      v.w - __bfloat162float(hb.y));
            int o = r * 72 + k4;
            *reinterpret_cast<__nv_bfloat162*>(Whi + o)     = ha;
            *reinterpret_cast<__nv_bfloat162*>(Whi + o + 2) = hb;
            *reinterpret_cast<__nv_bfloat162*>(Wlo + o)     = la;
            *reinterpret_cast<__nv_bfloat162*>(Wlo + o + 2) = lb;
        }
        __syncthreads();

#pragma unroll
        for (int kofs = 0; kofs < 64; kofs += 32) {
            uint32_t Ah[2][4], Al[2][4];
            ldsm_x4(Ah[0], a_hi + ((kofs      ) << 1));
            ldsm_x4(Ah[1], a_hi + ((kofs + 16 ) << 1));
            ldsm_x4(Al[0], a_lo + ((kofs      ) << 1));
            ldsm_x4(Al[1], a_lo + ((kofs + 16 ) << 1));

            uint32_t bh = b_hi + (kofs << 1);
#pragma unroll
            for (int jp = 0; jp < 8; jp++) {
                uint32_t B0h[4], B0l[4], B1h[4], B1l[4];
                ldsm_x4(B0h, bh);                    ldsm_x4(B0l, bh + PLANE);
                ldsm_x4(B1h, bh + 1152);             ldsm_x4(B1l, bh + 1152 + PLANE);
                bh += 2304;
                float* c0 = c[jp << 1];
                float* c1 = c[(jp << 1) + 1];
                mma_bf16(c0, Ah[0], B0h[0], B0h[1]); mma_bf16(c1, Ah[0], B1h[0], B1h[1]);
                mma_bf16(c0, Ah[1], B0h[2], B0h[3]); mma_bf16(c1, Ah[1], B1h[2], B1h[3]);
                mma_bf16(c0, Al[0], B0h[0], B0h[1]); mma_bf16(c1, Al[0], B1h[0], B1h[1]);
                mma_bf16(c0, Al[1], B0h[2], B0h[3]); mma_bf16(c1, Al[1], B1h[2], B1h[3]);
                mma_bf16(c0, Ah[0], B0l[0], B0l[1]); mma_bf16(c1, Ah[0], B1l[0], B1l[1]);
                mma_bf16(c0, Ah[1], B0l[2], B0l[3]); mma_bf16(c1, Ah[1], B1l[2], B1l[3]);
            }
        }
    }

    // ---- epilogue: bias + gate-pair stores ----
    const int dg = cid >> 2, dtq = cid & 3;
    const int mrow0 = m0 + (wid << 4) + dg;
#pragma unroll
    for (int j = 0; j < 16; j++) {
        int cp = (j << 3) + (dtq << 1);          // c-row pair (cp, cp+1)
        int nn = cp >> 2, g = cp & 3;            // g in {0,2}
        float bva = bsh[cp], bvb = bsh[cp + 1];
        size_t o0 = (size_t)mrow0 * 1024 + ((n0 + nn) << 2) + g;
        size_t o1 = (size_t)(mrow0 + 8) * 1024 + ((n0 + nn) << 2) + g;
        *reinterpret_cast<float2*>(out + o0) = make_float2(c[j][0] + bva, c[j][1] + bvb);
        *reinterpret_cast<float2*>(out + o1) = make_float2(c[j][2] + bva, c[j][3] + bvb);
    }
}

// ---- persistent LSTM recurrence, split-bf16 tensor-core dot (R13, proven) ----
// SMEM map (bytes): Whi [0,67584) | Wlo [67584,135168) | stg [135168,155648)
//                   red [155648,221184)
__global__ void __launch_bounds__(256, 1) rec_kernel(
    const float* __restrict__ xg, const float* __restrict__ Whh,
    float* __restrict__ hist)
{
    extern __shared__ char smc[];
    __nv_bfloat16* Whi = reinterpret_cast<__nv_bfloat16*>(smc);   // [128 c][264 k]
    __nv_bfloat16* Wlo = Whi + 128 * 264;
    float* red = reinterpret_cast<float*>(smc + 155648);

    const int bi = blockIdx.x >> 3, ni = blockIdx.x & 7;
    const int b0 = bi << 4, n0 = ni << 5;
    const int tid = threadIdx.x;
    const int kg  = tid >> 5;
    const int cid = tid & 31;

    for (int idx = tid; idx < 128 * 256; idx += 256) {
        int c = idx >> 8, k = idx & 255;
        int row = ((c & 3) << 8) + n0 + (c >> 2);
        float w = Whh[(size_t)row * 256 + k];
        __nv_bfloat16 h = __float2bfloat16(w);
        __nv_bfloat16 l = __float2bfloat16(w - __bfloat162float(h));
        Whi[c * 264 + k] = h;
        Wlo[c * 264 + k] = l;
    }
    __syncthreads();

    const int p0i = tid << 1;
    const int eb  = p0i >> 5, enn = p0i & 31;

    const unsigned* prodcnt = g_bar + (bi << 3) + kg;
    unsigned* mycnt = g_bar + (bi << 3) + ni;

    char* stgW = smc + 135168 + kg * 2560;
    const uint32_t stg_b = smem_u32(stgW);

    uint32_t aaddr[2][2];
    {
        int arow = cid & 15;
        int acolB = ((cid >> 4) << 3) * 2;
#pragma unroll
        for (int p = 0; p < 2; p++)
#pragma unroll
            for (int q = 0; q < 2; q++)
                aaddr[p][q] = stg_b + p * 1280 + arow * 80 + acolB + q * 32;
    }
    const uint32_t wbB = smem_u32(Whi);
    const uint32_t baddr0 = wbB + (((cid & 7) * 264) + (kg << 5) + ((cid >> 3) << 3)) * 2;
    const uint32_t BLO = 128 * 264 * 2;

    const int dg = cid >> 2, dtq = cid & 3;
    float* redw = red + (kg << 11) + (dg << 7) + (dtq << 1);

    const float4* xg4 = reinterpret_cast<const float4*>(xg);
    float creg[2] = {0.f, 0.f};

    for (int t = 0; t < TSEQ; t++) {
        size_t xi = ((size_t)t * BSZ + b0 + eb) * 256 + n0 + enn;
        ulonglong2 xq0 = *reinterpret_cast<const ulonglong2*>(&xg4[xi]);
        ulonglong2 xq1 = *reinterpret_cast<const ulonglong2*>(&xg4[xi + 1]);

        if (t > 0) {
            const unsigned tgt = (unsigned)t;
            while (ld_acq(prodcnt) < tgt) {}

            const float* hp = hist + ((size_t)(t - 1) * BSZ + b0) * HIDN + (kg << 5);
#pragma unroll
            for (int i = 0; i < 4; i++) {
                int f  = cid + (i << 5);
                int br = f >> 3, c4 = (f & 7) << 2;
                float4 v = *reinterpret_cast<const float4*>(hp + (br << 8) + c4);
                __nv_bfloat162 ha = __floats2bfloat162_rn(v.x, v.y);
                __nv_bfloat162 hb = __floats2bfloat162_rn(v.z, v.w);
                __nv_bfloat162 la = __floats2bfloat162_rn(v.x - __bfloat162float(ha.x),
                                                          v.y - __bfloat162float(ha.y));
                __nv_bfloat162 lb = __floats2bfloat162_rn(v.z - __bfloat162float(hb.x),
                                                          v.w - __bfloat162float(hb.y));
                char* dst = stgW + br * 80 + (c4 << 1);
                *reinterpret_cast<__nv_bfloat162*>(dst)        = ha;
                *reinterpret_cast<__nv_bfloat162*>(dst + 4)    = hb;
                *reinterpret_cast<__nv_bfloat162*>(dst + 1280) = la;
                *reinterpret_cast<__nv_bfloat162*>(dst + 1284) = lb;
            }
            __syncwarp();

            uint32_t Ah[2][4], Al[2][4];
            ldsm_x4(Ah[0], aaddr[0][0]); ldsm_x4(Ah[1], aaddr[0][1]);
            ldsm_x4(Al[0], aaddr[1][0]); ldsm_x4(Al[1], aaddr[1][1]);

            uint32_t bh = baddr0;
#pragma unroll
            for (int j = 0; j < 16; j += 2) {
                uint32_t B0h[4], B0l[4], B1h[4], B1l[4];
                ldsm_x4(B0h, bh);        ldsm_x4(B0l, bh + BLO);
                ldsm_x4(B1h, bh + 4224); ldsm_x4(B1l, bh + 4224 + BLO);
                bh += 8448;
                float c0[4] = {0.f,0.f,0.f,0.f}, c1[4] = {0.f,0.f,0.f,0.f};
                mma_bf16(c0, Ah[0], B0h[0], B0h[1]); mma_bf16(c1, Ah[0], B1h[0], B1h[1]);
                mma_bf16(c0, Ah[1], B0h[2], B0h[3]); mma_bf16(c1, Ah[1], B1h[2], B1h[3]);
                mma_bf16(c0, Al[0], B0h[0], B0h[1]); mma_bf16(c1, Al[0], B1h[0], B1h[1]);
                mma_bf16(c0, Al[1], B0h[2], B0h[3]); mma_bf16(c1, Al[1], B1h[2], B1h[3]);
                mma_bf16(c0, Ah[0], B0l[0], B0l[1]); mma_bf16(c1, Ah[0], B1l[0], B1l[1]);
                mma_bf16(c0, Ah[1], B0l[2], B0l[3]); mma_bf16(c1, Ah[1], B1l[2], B1l[3]);
                *reinterpret_cast<float2*>(redw + (j << 3))          = make_float2(c0[0], c0[1]);
                *reinterpret_cast<float2*>(redw + (j << 3) + 1024)   = make_float2(c0[2], c0[3]);
                *reinterpret_cast<float2*>(redw + (j << 3) + 8)      = make_float2(c1[0], c1[1]);
                *reinterpret_cast<float2*>(redw + (j << 3) + 8+1024) = make_float2(c1[2], c1[3]);
            }
        } else {
            float4 z = make_float4(0.f, 0.f, 0.f, 0.f);
            for (int i = cid; i < 512; i += 32)
                *reinterpret_cast<float4*>(red + (kg << 11) + (i << 2)) = z;
        }
        __syncthreads();

        float* ho = hist + ((size_t)t * BSZ + b0 + eb) * HIDN + n0 + enn;
        float hout[2];
#pragma unroll
        for (int pp = 0; pp < 2; pp++) {
            int cell = (eb << 5) + enn + pp;
            ull s01 = pp ? xq1.x : xq0.x;
            ull s23 = pp ? xq1.y : xq0.y;
            const float* rb = red + (cell << 2);
#pragma unroll
            for (int s = 0; s < 8; s++) {
                ulonglong2 r = *reinterpret_cast<const ulonglong2*>(rb + (s << 11));
                s01 = add2(s01, r.x);
                s23 = add2(s23, r.y);
            }
            float2 g01 = unpk(s01), g23 = unpk(s23);
            float cn = sigm(g01.y) * creg[pp] + sigm(g01.x) * ftanh(g23.x);
            creg[pp] = cn;
            hout[pp] = sigm(g23.y) * ftanh(cn);
        }
        *reinterpret_cast<float2*>(ho) = make_float2(hout[0], hout[1]);

        __syncthreads();
        if (tid == 0) red_rel_add(mycnt, 1u);
    }
}

// ---- head ----
__global__ void head_kernel(const float* __restrict__ Wh, const float* __restrict__ bh,
                            float* __restrict__ out)
{
    __shared__ float rs[8];
    int b = blockIdx.x, tid = threadIdx.x;
    float v = g_hist1[((size_t)(TSEQ - 1) * BSZ + b) * HIDN + tid] * Wh[tid];
#pragma unroll
    for (int o = 16; o > 0; o >>= 1) v += __shfl_down_sync(0xffffffffu, v, o);
    if ((tid & 31) == 0) rs[tid >> 5] = v;
    __syncthreads();
    if (tid < 8) {
        float s = rs[tid];
#pragma unroll
        for (int o = 4; o > 0; o >>= 1) s += __shfl_down_sync(0xffu, s, o);
        if (tid == 0) out[b] = s + bh[0];
    }
}

extern "C" void kernel_launch(void* const* d_in, const int* in_sizes, int n_in,
                              void* d_out, int out_size)
{
    const float* x      = (const float*)d_in[0];
    const float* W_ih0  = (const float*)d_in[1];
    const float* W_hh0  = (const float*)d_in[2];
    const float* b_ih0  = (const float*)d_in[3];
    const float* b_hh0  = (const float*)d_in[4];
    const float* W_ih1  = (const float*)d_in[5];
    const float* W_hh1  = (const float*)d_in[6];
    const float* b_ih1  = (const float*)d_in[7];
    const float* b_hh1  = (const float*)d_in[8];
    const float* W_head = (const float*)d_in[9];
    const float* b_head = (const float*)d_in[10];
    float* out = (float*)d_out;

    void *pxg, *ph0, *ph1;
    cudaGetSymbolAddress(&pxg, g_xg);
    cudaGetSymbolAddress(&ph0, g_hist0);
    cudaGetSymbolAddress(&ph1, g_hist1);
    float* xg = (float*)pxg; float* h0 = (float*)ph0; float* h1 = (float*)ph1;

    const int SMEM_R = 221184;
    const int SMEM_G = 74240;
    cudaFuncSetAttribute(rec_kernel, cudaFuncAttributeMaxDynamicSharedMemorySize, SMEM_R);
    cudaFuncSetAttribute(gemm_bf16<64,  true >, cudaFuncAttributeMaxDynamicSharedMemorySize, SMEM_G);
    cudaFuncSetAttribute(gemm_bf16<256, false>, cudaFuncAttributeMaxDynamicSharedMemorySize, SMEM_G);

    dim3 gg(1024, 8);
    gemm_bf16<64,  true ><<<gg, 256, SMEM_G>>>(x,  W_ih0, b_ih0, b_hh0, xg);
    reset_bar<<<1, 128>>>();
    rec_kernel<<<128, 256, SMEM_R>>>(xg, W_hh0, h0);
    gemm_bf16<256, false><<<gg, 256, SMEM_G>>>(h0, W_ih1, b_ih1, b_hh1, xg);
    reset_bar<<<1, 128>>>();
    rec_kernel<<<128, 256, SMEM_R>>>(xg, W_hh1, h1);
    head_kernel<<<256, 256>>>(W_head, b_head, out);
}

// round 16
// speedup vs baseline: 1.9932x; 1.1785x over previous
#include <cuda_runtime.h>
#include <cuda_bf16.h>
#include <cstdint>

#define BSZ  256
#define TSEQ 512
#define HIDN 256

typedef unsigned long long ull;

// ---- static scratch ----
// xg layout: [t][b][n][4] (gate quads)
__device__ float g_xg[(size_t)TSEQ * BSZ * 1024];
__device__ float g_hist0[(size_t)TSEQ * BSZ * HIDN];
__device__ float g_hist1[(size_t)TSEQ * BSZ * HIDN];
__device__ unsigned g_bar[16];    // one counter per batch-group (8 arrivals/step)

__global__ void reset_bar() { if (threadIdx.x < 16) g_bar[threadIdx.x] = 0u; }

__device__ __forceinline__ float sigm(float x) { return 1.f / (1.f + __expf(-x)); }
__device__ __forceinline__ float ftanh(float x) {
    float e = __expf(-2.f * fabsf(x));
    return copysignf((1.f - e) / (1.f + e), x);
}

// ---- scoped sync ----
__device__ __forceinline__ unsigned ld_acq(const unsigned* p) {
    unsigned v; asm volatile("ld.acquire.gpu.global.b32 %0, [%1];" : "=r"(v) : "l"(p)); return v;
}
__device__ __forceinline__ void red_rel_add(unsigned* p, unsigned v) {
    asm volatile("red.release.gpu.global.add.u32 [%0], %1;" :: "l"(p), "r"(v) : "memory");
}

// ---- smem helpers ----
__device__ __forceinline__ uint32_t smem_u32(const void* p) {
    uint32_t a;
    asm("{ .reg .u64 t; cvta.to.shared.u64 t, %1; cvt.u32.u64 %0, t; }" : "=r"(a) : "l"(p));
    return a;
}

// ---- tensor core primitives ----
__device__ __forceinline__ void ldsm_x4(uint32_t* r, uint32_t addr) {
    asm volatile("ldmatrix.sync.aligned.m8n8.x4.shared.b16 {%0,%1,%2,%3}, [%4];"
        : "=r"(r[0]), "=r"(r[1]), "=r"(r[2]), "=r"(r[3]) : "r"(addr));
}
__device__ __forceinline__ void mma_bf16(float* c, const uint32_t* a, uint32_t b0, uint32_t b1) {
    asm volatile("mma.sync.aligned.m16n8k16.row.col.f32.bf16.bf16.f32 "
        "{%0,%1,%2,%3}, {%4,%5,%6,%7}, {%8,%9}, {%0,%1,%2,%3};"
        : "+f"(c[0]), "+f"(c[1]), "+f"(c[2]), "+f"(c[3])
        : "r"(a[0]), "r"(a[1]), "r"(a[2]), "r"(a[3]), "r"(b0), "r"(b1));
}

// =======================================================================
// GEMM (split-bf16 HMMA) — unchanged from R14 (proven)
// =======================================================================
template<int K, bool XMODE>
__global__ void __launch_bounds__(256) gemm_bf16(
    const float* __restrict__ A, const float* __restrict__ W,
    const float* __restrict__ b1, const float* __restrict__ b2,
    float* __restrict__ out)
{
    extern __shared__ char smg[];
    const int PLANE = 18432;
    __nv_bfloat16* Ahi = reinterpret_cast<__nv_bfloat16*>(smg);
    __nv_bfloat16* Alo = reinterpret_cast<__nv_bfloat16*>(smg + 18432);
    __nv_bfloat16* Whi = reinterpret_cast<__nv_bfloat16*>(smg + 36864);
    __nv_bfloat16* Wlo = reinterpret_cast<__nv_bfloat16*>(smg + 55296);
    float* bsh = reinterpret_cast<float*>(smg + 73728);

    const int m0 = blockIdx.x * 128, n0 = blockIdx.y * 32;
    const int tid = threadIdx.x;
    const int wid = tid >> 5, cid = tid & 31;

    if (tid < 128) {
        int row = ((tid & 3) << 8) + n0 + (tid >> 2);
        bsh[tid] = b1[row] + b2[row];
    }

    float c[16][4];
#pragma unroll
    for (int j = 0; j < 16; j++)
#pragma unroll
        for (int q = 0; q < 4; q++) c[j][q] = 0.f;

    const uint32_t a_hi = smem_u32(Ahi) + ((wid << 4) + (cid & 15)) * 144 + ((cid >> 4) << 4);
    const uint32_t a_lo = a_hi + PLANE;
    const uint32_t b_hi = smem_u32(Whi) + (cid & 7) * 144 + ((cid >> 3) << 4);

    for (int kt = 0; kt < K; kt += 64) {
        __syncthreads();
#pragma unroll
        for (int i = 0; i < 8; i++) {
            int idx = tid + (i << 8);
            int r = idx >> 4, k4 = (idx & 15) << 2;
            int row = m0 + r;
            size_t aoff;
            if (XMODE) aoff = ((size_t)(row & 255) * TSEQ + (row >> 8)) * K;
            else       aoff = (size_t)row * K;
            float4 v = *reinterpret_cast<const float4*>(A + aoff + kt + k4);
            __nv_bfloat162 ha = __floats2bfloat162_rn(v.x, v.y);
            __nv_bfloat162 hb = __floats2bfloat162_rn(v.z, v.w);
            __nv_bfloat162 la = __floats2bfloat162_rn(v.x - __bfloat162float(ha.x),
                                                      v.y - __bfloat162float(ha.y));
            __nv_bfloat162 lb = __floats2bfloat162_rn(v.z - __bfloat162float(hb.x),
                                                      v.w - __bfloat162float(hb.y));
            int o = r * 72 + k4;
            *reinterpret_cast<__nv_bfloat162*>(Ahi + o)     = ha;
            *reinterpret_cast<__nv_bfloat162*>(Ahi + o + 2) = hb;
            *reinterpret_cast<__nv_bfloat162*>(Alo + o)     = la;
            *reinterpret_cast<__nv_bfloat162*>(Alo + o + 2) = lb;
        }
#pragma unroll
        for (int i = 0; i < 8; i++) {
            int idx = tid + (i << 8);
            int r = idx >> 4, k4 = (idx & 15) << 2;
            int wrow = ((r & 3) << 8) + n0 + (r >> 2);
            float4 v = *reinterpret_cast<const float4*>(W + (size_t)wrow * K + kt + k4);
            __nv_bfloat162 ha = __floats2bfloat162_rn(v.x, v.y);
            __nv_bfloat162 hb = __floats2bfloat162_rn(v.z, v.w);
            __nv_bfloat162 la = __floats2bfloat162_rn(v.x - __bfloat162float(ha.x),
                                                      v.y - __bfloat162float(ha.y));
            __nv_bfloat162 lb = __floats2bfloat162_rn(v.z - __bfloat162float(hb.x),
                                                      v.w - __bfloat162float(hb.y));
            int o = r * 72 + k4;
            *reinterpret_cast<__nv_bfloat162*>(Whi + o)     = ha;
            *reinterpret_cast<__nv_bfloat162*>(Whi + o + 2) = hb;
            *reinterpret_cast<__nv_bfloat162*>(Wlo + o)     = la;
            *reinterpret_cast<__nv_bfloat162*>(Wlo + o + 2) = lb;
        }
        __syncthreads();

#pragma unroll
        for (int kofs = 0; kofs < 64; kofs += 32) {
            uint32_t Ah[2][4], Al[2][4];
            ldsm_x4(Ah[0], a_hi + ((kofs      ) << 1));
            ldsm_x4(Ah[1], a_hi + ((kofs + 16 ) << 1));
            ldsm_x4(Al[0], a_lo + ((kofs      ) << 1));
            ldsm_x4(Al[1], a_lo + ((kofs + 16 ) << 1));

            uint32_t bh = b_hi + (kofs << 1);
#pragma unroll
            for (int jp = 0; jp < 8; jp++) {
                uint32_t B0h[4], B0l[4], B1h[4], B1l[4];
                ldsm_x4(B0h, bh);                    ldsm_x4(B0l, bh + PLANE);
                ldsm_x4(B1h, bh + 1152);             ldsm_x4(B1l, bh + 1152 + PLANE);
                bh += 2304;
                float* c0 = c[jp << 1];
                float* c1 = c[(jp << 1) + 1];
                mma_bf16(c0, Ah[0], B0h[0], B0h[1]); mma_bf16(c1, Ah[0], B1h[0], B1h[1]);
                mma_bf16(c0, Ah[1], B0h[2], B0h[3]); mma_bf16(c1, Ah[1], B1h[2], B1h[3]);
                mma_bf16(c0, Al[0], B0h[0], B0h[1]); mma_bf16(c1, Al[0], B1h[0], B1h[1]);
                mma_bf16(c0, Al[1], B0h[2], B0h[3]); mma_bf16(c1, Al[1], B1h[2], B1h[3]);
                mma_bf16(c0, Ah[0], B0l[0], B0l[1]); mma_bf16(c1, Ah[0], B1l[0], B1l[1]);
                mma_bf16(c0, Ah[1], B0l[2], B0l[3]); mma_bf16(c1, Ah[1], B1l[2], B1l[3]);
            }
        }
    }

    const int dg = cid >> 2, dtq = cid & 3;
    const int mrow0 = m0 + (wid << 4) + dg;
#pragma unroll
    for (int j = 0; j < 16; j++) {
        int cp = (j << 3) + (dtq << 1);
        int nn = cp >> 2, g = cp & 3;
        float bva = bsh[cp], bvb = bsh[cp + 1];
        size_t o0 = (size_t)mrow0 * 1024 + ((n0 + nn) << 2) + g;
        size_t o1 = (size_t)(mrow0 + 8) * 1024 + ((n0 + nn) << 2) + g;
        *reinterpret_cast<float2*>(out + o0) = make_float2(c[j][0] + bva, c[j][1] + bvb);
        *reinterpret_cast<float2*>(out + o1) = make_float2(c[j][2] + bva, c[j][3] + bvb);
    }
}

// =======================================================================
// Persistent LSTM recurrence — N-split warp tiles, full-K register accum.
// 128 CTAs = 16 batch-groups x 8 n-groups. Warp wid owns c-cols
// [16wid,16wid+16) (4 n-cells x 4 gates) x 16 batches x K=256.
// SMEM (bytes): Whi [0,67584) [128c][264k] | Wlo [67584,135168)
//               Hhi [135168,143616) [16b][264k] | Hlo [143616,152064)
//               xch [152064,160256)  8 warps x [16b][16c] fp32
// =======================================================================
__global__ void __launch_bounds__(256, 1) rec_kernel(
    const float* __restrict__ xg, const float* __restrict__ Whh,
    float* __restrict__ hist)
{
    extern __shared__ char smc[];
    __nv_bfloat16* Whi = reinterpret_cast<__nv_bfloat16*>(smc);
    __nv_bfloat16* Hhi = reinterpret_cast<__nv_bfloat16*>(smc + 135168);
    __nv_bfloat16* Hlo = reinterpret_cast<__nv_bfloat16*>(smc + 143616);
    float* xch = reinterpret_cast<float*>(smc + 152064);

    const int bi = blockIdx.x >> 3, ni = blockIdx.x & 7;
    const int b0 = bi << 4, n0 = ni << 5;
    const int tid = threadIdx.x;
    const int wid = tid >> 5, cid = tid & 31;

    // ---- split W_hh slice into bf16 hi/lo planes: W*[c][k], c = nn*4+g ----
    {
        __nv_bfloat16* Wlo = Whi + 128 * 264;
        for (int idx = tid; idx < 128 * 256; idx += 256) {
            int c = idx >> 8, k = idx & 255;
            int row = ((c & 3) << 8) + n0 + (c >> 2);
            float w = Whh[(size_t)row * 256 + k];
            __nv_bfloat16 h = __float2bfloat16(w);
            __nv_bfloat16 l = __float2bfloat16(w - __bfloat162float(h));
            Whi[c * 264 + k] = h;
            Wlo[c * 264 + k] = l;
        }
    }
    __syncthreads();

    unsigned* grp = g_bar + bi;

    // ldmatrix A (h) addresses: [16 rows][264 pitch], planes 8448B apart
    const uint32_t hB = smem_u32(Hhi);
    const uint32_t a_base = hB + (cid & 15) * 528 + ((cid >> 4) << 4);
    // ldmatrix B (W) bases: warp's two n8 tiles (c-rows 16wid+, 16wid+8+)
    const uint32_t wB = smem_u32(Whi);
    const uint32_t b_base0 = wB + ((wid << 4) + (cid & 7)) * 528 + ((cid >> 3) << 4);
    const uint32_t b_base1 = b_base0 + 8 * 528;
    const uint32_t BLO = 67584;   // hi->lo plane offset (bytes)

    // exchange tile
    float* xchW = xch + (wid << 8);
    const int dg = cid >> 2, dtq = cid & 3;

    // epilogue cells: p = 2cid+pp -> b = p>>2, nn_local = p&3 (pair shares b)
    const int ebb  = (cid << 1) >> 2;        // batch of both cells
    const int nnl0 = (cid << 1) & 3;         // 0 or 2
    const int ncol = n0 + (wid << 2) + nnl0; // global n of cell 0

    const float4* xg4 = reinterpret_cast<const float4*>(xg);
    float creg[2] = {0.f, 0.f};

    for (int t = 0; t < TSEQ; t++) {
        // prefetch gate quads (independent of h)
        size_t xi = ((size_t)t * BSZ + b0 + ebb) * 256 + ncol;
        float4 xv0 = __ldg(&xg4[xi]);
        float4 xv1 = __ldg(&xg4[xi + 1]);

        if (t > 0) {
            // wait for all 8 producers of step t-1
            const unsigned tgt = (unsigned)(t << 3);
            while (ld_acq(grp) < tgt) {}

            // cooperative stage: h(t-1) [16][256] fp32 -> bf16 hi/lo planes
            const float* hp = hist + ((size_t)(t - 1) * BSZ + b0) * HIDN;
#pragma unroll
            for (int i = 0; i < 4; i++) {
                int idx = tid + (i << 8);
                int b = idx >> 6, c4 = (idx & 63) << 2;
                float4 v = *reinterpret_cast<const float4*>(hp + (b << 8) + c4);
                __nv_bfloat162 ha = __floats2bfloat162_rn(v.x, v.y);
                __nv_bfloat162 hb = __floats2bfloat162_rn(v.z, v.w);
                __nv_bfloat162 la = __floats2bfloat162_rn(v.x - __bfloat162float(ha.x),
                                                          v.y - __bfloat162float(ha.y));
                __nv_bfloat162 lb = __floats2bfloat162_rn(v.z - __bfloat162float(hb.x),
                                                          v.w - __bfloat162float(hb.y));
                int o = b * 264 + c4;
                *reinterpret_cast<__nv_bfloat162*>(Hhi + o)     = ha;
                *reinterpret_cast<__nv_bfloat162*>(Hhi + o + 2) = hb;
                *reinterpret_cast<__nv_bfloat162*>(Hlo + o)     = la;
                *reinterpret_cast<__nv_bfloat162*>(Hlo + o + 2) = lb;
            }
            __syncthreads();

            // dot: full K in registers, 8 k32 chunks
            float c0[4] = {0.f,0.f,0.f,0.f}, c1[4] = {0.f,0.f,0.f,0.f};
            uint32_t ab = a_base, bb0 = b_base0, bb1 = b_base1;
#pragma unroll
            for (int kk = 0; kk < 8; kk++) {
                uint32_t Ah[2][4], Al[2][4];
                ldsm_x4(Ah[0], ab);          ldsm_x4(Ah[1], ab + 32);
                ldsm_x4(Al[0], ab + 8448);   ldsm_x4(Al[1], ab + 8448 + 32);
                uint32_t B0h[4], B0l[4], B1h[4], B1l[4];
                ldsm_x4(B0h, bb0);           ldsm_x4(B0l, bb0 + BLO);
                ldsm_x4(B1h, bb1);           ldsm_x4(B1l, bb1 + BLO);
                ab += 64; bb0 += 64; bb1 += 64;
                mma_bf16(c0, Ah[0], B0h[0], B0h[1]); mma_bf16(c1, Ah[0], B1h[0], B1h[1]);
                mma_bf16(c0, Ah[1], B0h[2], B0h[3]); mma_bf16(c1, Ah[1], B1h[2], B1h[3]);
                mma_bf16(c0, Al[0], B0h[0], B0h[1]); mma_bf16(c1, Al[0], B1h[0], B1h[1]);
                mma_bf16(c0, Al[1], B0h[2], B0h[3]); mma_bf16(c1, Al[1], B1h[2], B1h[3]);
                mma_bf16(c0, Ah[0], B0l[0], B0l[1]); mma_bf16(c1, Ah[0], B1l[0], B1l[1]);
                mma_bf16(c0, Ah[1], B0l[2], B0l[3]); mma_bf16(c1, Ah[1], B1l[2], B1l[3]);
            }

            // D fragments -> warp exchange tile [16b][16c]
            *reinterpret_cast<float2*>(xchW + (dg    ) * 16 + (dtq << 1))     = make_float2(c0[0], c0[1]);
            *reinterpret_cast<float2*>(xchW + (dg + 8) * 16 + (dtq << 1))     = make_float2(c0[2], c0[3]);
            *reinterpret_cast<float2*>(xchW + (dg    ) * 16 + 8 + (dtq << 1)) = make_float2(c1[0], c1[1]);
            *reinterpret_cast<float2*>(xchW + (dg + 8) * 16 + 8 + (dtq << 1)) = make_float2(c1[2], c1[3]);
            __syncwarp();
        } else {
            float4 z = make_float4(0.f, 0.f, 0.f, 0.f);
#pragma unroll
            for (int i = 0; i < 2; i++)
                *reinterpret_cast<float4*>(xchW + ((cid + (i << 5)) << 2)) = z;
            __syncwarp();
        }

        // epilogue: read own cells' gate quads from exchange tile
        float hout[2];
#pragma unroll
        for (int pp = 0; pp < 2; pp++) {
            float4 gq = *reinterpret_cast<const float4*>(xchW + ebb * 16 + (nnl0 + pp) * 4);
            float4 xv = pp ? xv1 : xv0;
            float gi = gq.x + xv.x, gf = gq.y + xv.y;
            float gg = gq.z + xv.z, go = gq.w + xv.w;
            float cn = sigm(gf) * creg[pp] + sigm(gi) * ftanh(gg);
            creg[pp] = cn;
            hout[pp] = sigm(go) * ftanh(cn);
        }
        *reinterpret_cast<float2*>(
            hist + ((size_t)t * BSZ + b0 + ebb) * HIDN + ncol) = make_float2(hout[0], hout[1]);

        __syncthreads();                      // h stores done; Hhi/xch reuse safe
        if (tid == 0) red_rel_add(grp, 1u);   // publish step t
    }
}

// ---- head ----
__global__ void head_kernel(const float* __restrict__ Wh, const float* __restrict__ bh,
                            float* __restrict__ out)
{
    __shared__ float rs[8];
    int b = blockIdx.x, tid = threadIdx.x;
    float v = g_hist1[((size_t)(TSEQ - 1) * BSZ + b) * HIDN + tid] * Wh[tid];
#pragma unroll
    for (int o = 16; o > 0; o >>= 1) v += __shfl_down_sync(0xffffffffu, v, o);
    if ((tid & 31) == 0) rs[tid >> 5] = v;
    __syncthreads();
    if (tid < 8) {
        float s = rs[tid];
#pragma unroll
        for (int o = 4; o > 0; o >>= 1) s += __shfl_down_sync(0xffu, s, o);
        if (tid == 0) out[b] = s + bh[0];
    }
}

extern "C" void kernel_launch(void* const* d_in, const int* in_sizes, int n_in,
                              void* d_out, int out_size)
{
    const float* x      = (const float*)d_in[0];
    const float* W_ih0  = (const float*)d_in[1];
    const float* W_hh0  = (const float*)d_in[2];
    const float* b_ih0  = (const float*)d_in[3];
    const float* b_hh0  = (const float*)d_in[4];
    const float* W_ih1  = (const float*)d_in[5];
    const float* W_hh1  = (const float*)d_in[6];
    const float* b_ih1  = (const float*)d_in[7];
    const float* b_hh1  = (const float*)d_in[8];
    const float* W_head = (const float*)d_in[9];
    const float* b_head = (const float*)d_in[10];
    float* out = (float*)d_out;

    void *pxg, *ph0, *ph1;
    cudaGetSymbolAddress(&pxg, g_xg);
    cudaGetSymbolAddress(&ph0, g_hist0);
    cudaGetSymbolAddress(&ph1, g_hist1);
    float* xg = (float*)pxg; float* h0 = (float*)ph0; float* h1 = (float*)ph1;

    const int SMEM_R = 160256;
    const int SMEM_G = 74240;
    cudaFuncSetAttribute(rec_kernel, cudaFuncAttributeMaxDynamicSharedMemorySize, SMEM_R);
    cudaFuncSetAttribute(gemm_bf16<64,  true >, cudaFuncAttributeMaxDynamicSharedMemorySize, SMEM_G);
    cudaFuncSetAttribute(gemm_bf16<256, false>, cudaFuncAttributeMaxDynamicSharedMemorySize, SMEM_G);

    dim3 gg(1024, 8);
    gemm_bf16<64,  true ><<<gg, 256, SMEM_G>>>(x,  W_ih0, b_ih0, b_hh0, xg);
    reset_bar<<<1, 32>>>();
    rec_kernel<<<128, 256, SMEM_R>>>(xg, W_hh0, h0);
    gemm_bf16<256, false><<<gg, 256, SMEM_G>>>(h0, W_ih1, b_ih1, b_hh1, xg);
    reset_bar<<<1, 32>>>();
    rec_kernel<<<128, 256, SMEM_R>>>(xg, W_hh1, h1);
    head_kernel<<<256, 256>>>(W_head, b_head, out);
}

// round 17
// speedup vs baseline: 2.1089x; 1.0580x over previous
#include <cuda_runtime.h>
#include <cuda_bf16.h>
#include <cstdint>

#define BSZ  256
#define TSEQ 512
#define HIDN 256

typedef unsigned long long ull;

// ---- static scratch ----
// xg layout: [t][b][n][4] (gate quads)
__device__ float g_xg[(size_t)TSEQ * BSZ * 1024];
__device__ float g_hist0[(size_t)TSEQ * BSZ * HIDN];
__device__ float g_hist1[(size_t)TSEQ * BSZ * HIDN];
__device__ unsigned g_bar[16];    // one counter per batch-group (8 arrivals/step)

__global__ void reset_bar() { if (threadIdx.x < 16) g_bar[threadIdx.x] = 0u; }

__device__ __forceinline__ float sigm(float x) { return 1.f / (1.f + __expf(-x)); }
__device__ __forceinline__ float ftanh(float x) {
    float e = __expf(-2.f * fabsf(x));
    return copysignf((1.f - e) / (1.f + e), x);
}

// ---- scoped sync ----
__device__ __forceinline__ unsigned ld_acq(const unsigned* p) {
    unsigned v; asm volatile("ld.acquire.gpu.global.b32 %0, [%1];" : "=r"(v) : "l"(p)); return v;
}
__device__ __forceinline__ void red_rel_add(unsigned* p, unsigned v) {
    asm volatile("red.release.gpu.global.add.u32 [%0], %1;" :: "l"(p), "r"(v) : "memory");
}

// ---- smem helpers ----
__device__ __forceinline__ uint32_t smem_u32(const void* p) {
    uint32_t a;
    asm("{ .reg .u64 t; cvta.to.shared.u64 t, %1; cvt.u32.u64 %0, t; }" : "=r"(a) : "l"(p));
    return a;
}

// ---- tensor core primitives ----
__device__ __forceinline__ void ldsm_x4(uint32_t* r, uint32_t addr) {
    asm volatile("ldmatrix.sync.aligned.m8n8.x4.shared.b16 {%0,%1,%2,%3}, [%4];"
        : "=r"(r[0]), "=r"(r[1]), "=r"(r[2]), "=r"(r[3]) : "r"(addr));
}
__device__ __forceinline__ void mma_bf16(float* c, const uint32_t* a, uint32_t b0, uint32_t b1) {
    asm volatile("mma.sync.aligned.m16n8k16.row.col.f32.bf16.bf16.f32 "
        "{%0,%1,%2,%3}, {%4,%5,%6,%7}, {%8,%9}, {%0,%1,%2,%3};"
        : "+f"(c[0]), "+f"(c[1]), "+f"(c[2]), "+f"(c[3])
        : "r"(a[0]), "r"(a[1]), "r"(a[2]), "r"(a[3]), "r"(b0), "r"(b1));
}

// =======================================================================
// GEMM (split-bf16 HMMA): R14 structure, now 2 CTAs/SM (regs capped 128)
// =======================================================================
template<int K, bool XMODE>
__global__ void __launch_bounds__(256, 2) gemm_bf16(
    const float* __restrict__ A, const float* __restrict__ W,
    const float* __restrict__ b1, const float* __restrict__ b2,
    float* __restrict__ out)
{
    extern __shared__ char smg[];
    const int PLANE = 18432;
    __nv_bfloat16* Ahi = reinterpret_cast<__nv_bfloat16*>(smg);
    __nv_bfloat16* Alo = reinterpret_cast<__nv_bfloat16*>(smg + 18432);
    __nv_bfloat16* Whi = reinterpret_cast<__nv_bfloat16*>(smg + 36864);
    __nv_bfloat16* Wlo = reinterpret_cast<__nv_bfloat16*>(smg + 55296);
    float* bsh = reinterpret_cast<float*>(smg + 73728);

    const int m0 = blockIdx.x * 128, n0 = blockIdx.y * 32;
    const int tid = threadIdx.x;
    const int wid = tid >> 5, cid = tid & 31;

    if (tid < 128) {
        int row = ((tid & 3) << 8) + n0 + (tid >> 2);
        bsh[tid] = b1[row] + b2[row];
    }

    float c[16][4];
#pragma unroll
    for (int j = 0; j < 16; j++)
#pragma unroll
        for (int q = 0; q < 4; q++) c[j][q] = 0.f;

    const uint32_t a_hi = smem_u32(Ahi) + ((wid << 4) + (cid & 15)) * 144 + ((cid >> 4) << 4);
    const uint32_t a_lo = a_hi + PLANE;
    const uint32_t b_hi = smem_u32(Whi) + (cid & 7) * 144 + ((cid >> 3) << 4);

    for (int kt = 0; kt < K; kt += 64) {
        __syncthreads();
#pragma unroll
        for (int i = 0; i < 8; i++) {
            int idx = tid + (i << 8);
            int r = idx >> 4, k4 = (idx & 15) << 2;
            int row = m0 + r;
            size_t aoff;
            if (XMODE) aoff = ((size_t)(row & 255) * TSEQ + (row >> 8)) * K;
            else       aoff = (size_t)row * K;
            float4 v = *reinterpret_cast<const float4*>(A + aoff + kt + k4);
            __nv_bfloat162 ha = __floats2bfloat162_rn(v.x, v.y);
            __nv_bfloat162 hb = __floats2bfloat162_rn(v.z, v.w);
            __nv_bfloat162 la = __floats2bfloat162_rn(v.x - __bfloat162float(ha.x),
                                                      v.y - __bfloat162float(ha.y));
            __nv_bfloat162 lb = __floats2bfloat162_rn(v.z - __bfloat162float(hb.x),
                                                      v.w - __bfloat162float(hb.y));
            int o = r * 72 + k4;
            *reinterpret_cast<__nv_bfloat162*>(Ahi + o)     = ha;
            *reinterpret_cast<__nv_bfloat162*>(Ahi + o + 2) = hb;
            *reinterpret_cast<__nv_bfloat162*>(Alo + o)     = la;
            *reinterpret_cast<__nv_bfloat162*>(Alo + o + 2) = lb;
        }
#pragma unroll
        for (int i = 0; i < 8; i++) {
            int idx = tid + (i << 8);
            int r = idx >> 4, k4 = (idx & 15) << 2;
            int wrow = ((r & 3) << 8) + n0 + (r >> 2);
            float4 v = *reinterpret_cast<const float4*>(W + (size_t)wrow * K + kt + k4);
            __nv_bfloat162 ha = __floats2bfloat162_rn(v.x, v.y);
            __nv_bfloat162 hb = __floats2bfloat162_rn(v.z, v.w);
            __nv_bfloat162 la = __floats2bfloat162_rn(v.x - __bfloat162float(ha.x),
                                                      v.y - __bfloat162float(ha.y));
            __nv_bfloat162 lb = __floats2bfloat162_rn(v.z - __bfloat162float(hb.x),
                                                      v.w - __bfloat162float(hb.y));
            int o = r * 72 + k4;
            *reinterpret_cast<__nv_bfloat162*>(Whi + o)     = ha;
            *reinterpret_cast<__nv_bfloat162*>(Whi + o + 2) = hb;
            *reinterpret_cast<__nv_bfloat162*>(Wlo + o)     = la;
            *reinterpret_cast<__nv_bfloat162*>(Wlo + o + 2) = lb;
        }
        __syncthreads();

#pragma unroll
        for (int kofs = 0; kofs < 64; kofs += 32) {
            uint32_t Ah[2][4], Al[2][4];
            ldsm_x4(Ah[0], a_hi + ((kofs      ) << 1));
            ldsm_x4(Ah[1], a_hi + ((kofs + 16 ) << 1));
            ldsm_x4(Al[0], a_lo + ((kofs      ) << 1));
            ldsm_x4(Al[1], a_lo + ((kofs + 16 ) << 1));

            uint32_t bh = b_hi + (kofs << 1);
#pragma unroll
            for (int jp = 0; jp < 8; jp++) {
                uint32_t B0h[4], B0l[4], B1h[4], B1l[4];
                ldsm_x4(B0h, bh);                    ldsm_x4(B0l, bh + PLANE);
                ldsm_x4(B1h, bh + 1152);             ldsm_x4(B1l, bh + 1152 + PLANE);
                bh += 2304;
                float* c0 = c[jp << 1];
                float* c1 = c[(jp << 1) + 1];
                mma_bf16(c0, Ah[0], B0h[0], B0h[1]); mma_bf16(c1, Ah[0], B1h[0], B1h[1]);
                mma_bf16(c0, Ah[1], B0h[2], B0h[3]); mma_bf16(c1, Ah[1], B1h[2], B1h[3]);
                mma_bf16(c0, Al[0], B0h[0], B0h[1]); mma_bf16(c1, Al[0], B1h[0], B1h[1]);
                mma_bf16(c0, Al[1], B0h[2], B0h[3]); mma_bf16(c1, Al[1], B1h[2], B1h[3]);
                mma_bf16(c0, Ah[0], B0l[0], B0l[1]); mma_bf16(c1, Ah[0], B1l[0], B1l[1]);
                mma_bf16(c0, Ah[1], B0l[2], B0l[3]); mma_bf16(c1, Ah[1], B1l[2], B1l[3]);
            }
        }
    }

    const int dg = cid >> 2, dtq = cid & 3;
    const int mrow0 = m0 + (wid << 4) + dg;
#pragma unroll
    for (int j = 0; j < 16; j++) {
        int cp = (j << 3) + (dtq << 1);
        int nn = cp >> 2, g = cp & 3;
        float bva = bsh[cp], bvb = bsh[cp + 1];
        size_t o0 = (size_t)mrow0 * 1024 + ((n0 + nn) << 2) + g;
        size_t o1 = (size_t)(mrow0 + 8) * 1024 + ((n0 + nn) << 2) + g;
        *reinterpret_cast<float2*>(out + o0) = make_float2(c[j][0] + bva, c[j][1] + bvb);
        *reinterpret_cast<float2*>(out + o1) = make_float2(c[j][2] + bva, c[j][3] + bvb);
    }
}

// =======================================================================
// Persistent LSTM recurrence — N-split warp tiles (R15, proven)
// =======================================================================
__global__ void __launch_bounds__(256, 1) rec_kernel(
    const float* __restrict__ xg, const float* __restrict__ Whh,
    float* __restrict__ hist)
{
    extern __shared__ char smc[];
    __nv_bfloat16* Whi = reinterpret_cast<__nv_bfloat16*>(smc);
    __nv_bfloat16* Hhi = reinterpret_cast<__nv_bfloat16*>(smc + 135168);
    __nv_bfloat16* Hlo = reinterpret_cast<__nv_bfloat16*>(smc + 143616);
    float* xch = reinterpret_cast<float*>(smc + 152064);

    const int bi = blockIdx.x >> 3, ni = blockIdx.x & 7;
    const int b0 = bi << 4, n0 = ni << 5;
    const int tid = threadIdx.x;
    const int wid = tid >> 5, cid = tid & 31;

    {
        __nv_bfloat16* Wlo = Whi + 128 * 264;
        for (int idx = tid; idx < 128 * 256; idx += 256) {
            int c = idx >> 8, k = idx & 255;
            int row = ((c & 3) << 8) + n0 + (c >> 2);
            float w = Whh[(size_t)row * 256 + k];
            __nv_bfloat16 h = __float2bfloat16(w);
            __nv_bfloat16 l = __float2bfloat16(w - __bfloat162float(h));
            Whi[c * 264 + k] = h;
            Wlo[c * 264 + k] = l;
        }
    }
    __syncthreads();

    unsigned* grp = g_bar + bi;

    const uint32_t hB = smem_u32(Hhi);
    const uint32_t a_base = hB + (cid & 15) * 528 + ((cid >> 4) << 4);
    const uint32_t wB = smem_u32(Whi);
    const uint32_t b_base0 = wB + ((wid << 4) + (cid & 7)) * 528 + ((cid >> 3) << 4);
    const uint32_t b_base1 = b_base0 + 8 * 528;
    const uint32_t BLO = 67584;

    float* xchW = xch + (wid << 8);
    const int dg = cid >> 2, dtq = cid & 3;

    const int ebb  = (cid << 1) >> 2;
    const int nnl0 = (cid << 1) & 3;
    const int ncol = n0 + (wid << 2) + nnl0;

    const float4* xg4 = reinterpret_cast<const float4*>(xg);
    float creg[2] = {0.f, 0.f};

    for (int t = 0; t < TSEQ; t++) {
        size_t xi = ((size_t)t * BSZ + b0 + ebb) * 256 + ncol;
        float4 xv0 = __ldg(&xg4[xi]);
        float4 xv1 = __ldg(&xg4[xi + 1]);

        if (t > 0) {
            const unsigned tgt = (unsigned)(t << 3);
            while (ld_acq(grp) < tgt) {}

            const float* hp = hist + ((size_t)(t - 1) * BSZ + b0) * HIDN;
#pragma unroll
            for (int i = 0; i < 4; i++) {
                int idx = tid + (i << 8);
                int b = idx >> 6, c4 = (idx & 63) << 2;
                float4 v = *reinterpret_cast<const float4*>(hp + (b << 8) + c4);
                __nv_bfloat162 ha = __floats2bfloat162_rn(v.x, v.y);
                __nv_bfloat162 hb = __floats2bfloat162_rn(v.z, v.w);
                __nv_bfloat162 la = __floats2bfloat162_rn(v.x - __bfloat162float(ha.x),
                                                          v.y - __bfloat162float(ha.y));
                __nv_bfloat162 lb = __floats2bfloat162_rn(v.z - __bfloat162float(hb.x),
                                                          v.w - __bfloat162float(hb.y));
                int o = b * 264 + c4;
                *reinterpret_cast<__nv_bfloat162*>(Hhi + o)     = ha;
                *reinterpret_cast<__nv_bfloat162*>(Hhi + o + 2) = hb;
                *reinterpret_cast<__nv_bfloat162*>(Hlo + o)     = la;
                *reinterpret_cast<__nv_bfloat162*>(Hlo + o + 2) = lb;
            }
            __syncthreads();

            float c0[4] = {0.f,0.f,0.f,0.f}, c1[4] = {0.f,0.f,0.f,0.f};
            uint32_t ab = a_base, bb0 = b_base0, bb1 = b_base1;
#pragma unroll
            for (int kk = 0; kk < 8; kk++) {
                uint32_t Ah[2][4], Al[2][4];
                ldsm_x4(Ah[0], ab);          ldsm_x4(Ah[1], ab + 32);
                ldsm_x4(Al[0], ab + 8448);   ldsm_x4(Al[1], ab + 8448 + 32);
                uint32_t B0h[4], B0l[4], B1h[4], B1l[4];
                ldsm_x4(B0h, bb0);           ldsm_x4(B0l, bb0 + BLO);
                ldsm_x4(B1h, bb1);           ldsm_x4(B1l, bb1 + BLO);
                ab += 64; bb0 += 64; bb1 += 64;
                mma_bf16(c0, Ah[0], B0h[0], B0h[1]); mma_bf16(c1, Ah[0], B1h[0], B1h[1]);
                mma_bf16(c0, Ah[1], B0h[2], B0h[3]); mma_bf16(c1, Ah[1], B1h[2], B1h[3]);
                mma_bf16(c0, Al[0], B0h[0], B0h[1]); mma_bf16(c1, Al[0], B1h[0], B1h[1]);
                mma_bf16(c0, Al[1], B0h[2], B0h[3]); mma_bf16(c1, Al[1], B1h[2], B1h[3]);
                mma_bf16(c0, Ah[0], B0l[0], B0l[1]); mma_bf16(c1, Ah[0], B1l[0], B1l[1]);
                mma_bf16(c0, Ah[1], B0l[2], B0l[3]); mma_bf16(c1, Ah[1], B1l[2], B1l[3]);
            }

            *reinterpret_cast<float2*>(xchW + (dg    ) * 16 + (dtq << 1))     = make_float2(c0[0], c0[1]);
            *reinterpret_cast<float2*>(xchW + (dg + 8) * 16 + (dtq << 1))     = make_float2(c0[2], c0[3]);
            *reinterpret_cast<float2*>(xchW + (dg    ) * 16 + 8 + (dtq << 1)) = make_float2(c1[0], c1[1]);
            *reinterpret_cast<float2*>(xchW + (dg + 8) * 16 + 8 + (dtq << 1)) = make_float2(c1[2], c1[3]);
            __syncwarp();
        } else {
            float4 z = make_float4(0.f, 0.f, 0.f, 0.f);
#pragma unroll
            for (int i = 0; i < 2; i++)
                *reinterpret_cast<float4*>(xchW + ((cid + (i << 5)) << 2)) = z;
            __syncwarp();
        }

        float hout[2];
#pragma unroll
        for (int pp = 0; pp < 2; pp++) {
            float4 gq = *reinterpret_cast<const float4*>(xchW + ebb * 16 + (nnl0 + pp) * 4);
            float4 xv = pp ? xv1 : xv0;
            float gi = gq.x + xv.x, gf = gq.y + xv.y;
            float gg = gq.z + xv.z, go = gq.w + xv.w;
            float cn = sigm(gf) * creg[pp] + sigm(gi) * ftanh(gg);
            creg[pp] = cn;
            hout[pp] = sigm(go) * ftanh(cn);
        }
        *reinterpret_cast<float2*>(
            hist + ((size_t)t * BSZ + b0 + ebb) * HIDN + ncol) = make_float2(hout[0], hout[1]);

        __syncthreads();
        if (tid == 0) red_rel_add(grp, 1u);
    }
}

// ---- head ----
__global__ void head_kernel(const float* __restrict__ Wh, const float* __restrict__ bh,
                            float* __restrict__ out)
{
    __shared__ float rs[8];
    int b = blockIdx.x, tid = threadIdx.x;
    float v = g_hist1[((size_t)(TSEQ - 1) * BSZ + b) * HIDN + tid] * Wh[tid];
#pragma unroll
    for (int o = 16; o > 0; o >>= 1) v += __shfl_down_sync(0xffffffffu, v, o);
    if ((tid & 31) == 0) rs[tid >> 5] = v;
    __syncthreads();
    if (tid < 8) {
        float s = rs[tid];
#pragma unroll
        for (int o = 4; o > 0; o >>= 1) s += __shfl_down_sync(0xffu, s, o);
        if (tid == 0) out[b] = s + bh[0];
    }
}

extern "C" void kernel_launch(void* const* d_in, const int* in_sizes, int n_in,
                              void* d_out, int out_size)
{
    const float* x      = (const float*)d_in[0];
    const float* W_ih0  = (const float*)d_in[1];
    const float* W_hh0  = (const float*)d_in[2];
    const float* b_ih0  = (const float*)d_in[3];
    const float* b_hh0  = (const float*)d_in[4];
    const float* W_ih1  = (const float*)d_in[5];
    const float* W_hh1  = (const float*)d_in[6];
    const float* b_ih1  = (const float*)d_in[7];
    const float* b_hh1  = (const float*)d_in[8];
    const float* W_head = (const float*)d_in[9];
    const float* b_head = (const float*)d_in[10];
    float* out = (float*)d_out;

    void *pxg, *ph0, *ph1;
    cudaGetSymbolAddress(&pxg, g_xg);
    cudaGetSymbolAddress(&ph0, g_hist0);
    cudaGetSymbolAddress(&ph1, g_hist1);
    float* xg = (float*)pxg; float* h0 = (float*)ph0; float* h1 = (float*)ph1;

    const int SMEM_R = 160256;
    const int SMEM_G = 74240;
    cudaFuncSetAttribute(rec_kernel, cudaFuncAttributeMaxDynamicSharedMemorySize, SMEM_R);
    cudaFuncSetAttribute(gemm_bf16<64,  true >, cudaFuncAttributeMaxDynamicSharedMemorySize, SMEM_G);
    cudaFuncSetAttribute(gemm_bf16<256, false>, cudaFuncAttributeMaxDynamicSharedMemorySize, SMEM_G);

    dim3 gg(1024, 8);
    gemm_bf16<64,  true ><<<gg, 256, SMEM_G>>>(x,  W_ih0, b_ih0, b_hh0, xg);
    reset_bar<<<1, 32>>>();
    rec_kernel<<<128, 256, SMEM_R>>>(xg, W_hh0, h0);
    gemm_bf16<256, false><<<gg, 256, SMEM_G>>>(h0, W_ih1, b_ih1, b_hh1, xg);
    reset_bar<<<1, 32>>>();
    rec_kernel<<<128, 256, SMEM_R>>>(xg, W_hh1, h1);
    head_kernel<<<256, 256>>>(W_head, b_head, out);
}